// round 7
// baseline (speedup 1.0000x reference)
#include <cuda_runtime.h>
#include <cuda_bf16.h>
#include <cuda_fp16.h>
#include <cstdint>

#define Bc 2
#define Cc 512
#define NHc 8
#define NPc 4
#define HDc 64
#define Dim 20
#define Nspat 8000          // 20*20*20
#define MTOT (Bc*Nspat)     // 16000
#define LN_EPS 1e-5f

// ---------------- scratch (no allocations allowed) ----------------
__device__ __align__(16) __nv_bfloat16 g_qH  [(size_t)MTOT*Cc];
__device__ __align__(16) __nv_bfloat16 g_qL  [(size_t)MTOT*Cc];
__device__ __align__(16) __nv_bfloat16 g_QH  [(size_t)MTOT*Cc];
__device__ __align__(16) __nv_bfloat16 g_QL  [(size_t)MTOT*Cc];
__device__ __align__(16) __nv_bfloat16 g_hidH[(size_t)MTOT*Cc];
__device__ __align__(16) __nv_bfloat16 g_hidL[(size_t)MTOT*Cc];
__device__ __align__(16) __nv_bfloat16 g_sH  [(size_t)MTOT*Cc];
__device__ __align__(16) __nv_bfloat16 g_sL  [(size_t)MTOT*Cc];
__device__ __align__(16) float g_off [(size_t)MTOT*NHc*NPc*3];
__device__ __align__(16) float g_attn[(size_t)MTOT*NHc*NPc];
__device__ __align__(16) __half g_feats[(size_t)Bc*NHc*Nspat*HDc];
// split/transposed weights: (Npad, 512) K-major, hi/lo bf16
__device__ __align__(256) __nv_bfloat16 g_WqH  [512*512];
__device__ __align__(256) __nv_bfloat16 g_WqL  [512*512];
__device__ __align__(256) __nv_bfloat16 g_Wo1H [512*512];
__device__ __align__(256) __nv_bfloat16 g_Wo1L [512*512];
__device__ __align__(256) __nv_bfloat16 g_WoutH[512*512];
__device__ __align__(256) __nv_bfloat16 g_WoutL[512*512];
__device__ __align__(256) __nv_bfloat16 g_Wo2H [128*512];
__device__ __align__(256) __nv_bfloat16 g_Wo2L [128*512];
__device__ __align__(256) __nv_bfloat16 g_WaH  [128*512];
__device__ __align__(256) __nv_bfloat16 g_WaL  [128*512];

// ================= helpers =================
__device__ __forceinline__ uint32_t smem_u32(const void* p) {
    uint32_t a;
    asm("{ .reg .u64 t; cvta.to.shared.u64 t, %1; cvt.u32.u64 %0, t; }" : "=r"(a) : "l"(p));
    return a;
}
__device__ __forceinline__ void ldsm4(uint32_t* r, uint32_t addr) {
    asm volatile("ldmatrix.sync.aligned.m8n8.x4.shared.b16 {%0,%1,%2,%3}, [%4];"
        : "=r"(r[0]), "=r"(r[1]), "=r"(r[2]), "=r"(r[3]) : "r"(addr));
}
__device__ __forceinline__ void mma_bf16(float* c, const uint32_t* a, const uint32_t* b) {
    asm volatile(
        "mma.sync.aligned.m16n8k16.row.col.f32.bf16.bf16.f32 "
        "{%0,%1,%2,%3}, {%4,%5,%6,%7}, {%8,%9}, {%0,%1,%2,%3};"
        : "+f"(c[0]), "+f"(c[1]), "+f"(c[2]), "+f"(c[3])
        : "r"(a[0]), "r"(a[1]), "r"(a[2]), "r"(a[3]), "r"(b[0]), "r"(b[1]));
}
#define CPA16(dst, src) \
    asm volatile("cp.async.cg.shared.global [%0], [%1], 16;" :: "r"(dst), "l"(src) : "memory")

// ================= split-bf16 HMMA GEMM (all operands pre-split) =================
// D = act(A(M,512)@W(512,Nc)+bias). A and W both (rows,512) K-major bf16 hi/lo.
// Tile 128x128, BK=32, 2-stage cp.async pipeline. 3 MMAs: hh + lh + hl.
// stage layout (80B row stride, 32 bf16/row): Ah@0 Al@10240 Bh@20480 Bl@30720
#define MG_STAGE 40960
#define MG_SMEM  (2*MG_STAGE)   // 80KB dynamic

// omode: 0 = fp32 row-major, 1 = fp32 transposed (B,C,Nspat) via smem staging, 2 = split bf16 H/L
__device__ __forceinline__ void sgemm_body(
    const __nv_bfloat16* __restrict__ AH, const __nv_bfloat16* __restrict__ AL,
    const __nv_bfloat16* __restrict__ BH, const __nv_bfloat16* __restrict__ BL,
    const float* __restrict__ bias,
    float* __restrict__ Cf, __nv_bfloat16* __restrict__ CH, __nv_bfloat16* __restrict__ CL,
    int Nc, int act, int omode, int m0, int n0, char* sm)
{
    const uint32_t smb = smem_u32(sm);
    const int tid = threadIdx.x;
    const int wid = tid >> 5, lane = tid & 31;
    const int wm = wid >> 1;
    const int wn = wid & 1;

    const int tq = lane >> 3, rr = lane & 7;
    const int a_row = rr + (tq & 1) * 8;
    const int a_col = (tq >> 1) * 8;
    const int b_row = rr + (tq >> 1) * 8;
    const int b_col = (tq & 1) * 8;

    const int r2  = tid >> 1;            // 0..127
    const int kc2 = (tid & 1) * 32;      // byte offset: 0 or 32

    const __nv_bfloat16* AHp = AH + (size_t)(m0 + r2) * 512 + (tid & 1) * 16;
    const __nv_bfloat16* ALp = AL + (size_t)(m0 + r2) * 512 + (tid & 1) * 16;
    const __nv_bfloat16* BHp = BH + (size_t)(n0 + r2) * 512 + (tid & 1) * 16;
    const __nv_bfloat16* BLp = BL + (size_t)(n0 + r2) * 512 + (tid & 1) * 16;

    auto ldAB = [&](int stage, int kt) {
        uint32_t ro = smb + stage * MG_STAGE + r2 * 80 + kc2;
        const int go = kt * 32;
        CPA16(ro,              AHp + go);
        CPA16(ro + 16,         AHp + go + 8);
        CPA16(ro + 10240,      ALp + go);
        CPA16(ro + 10240 + 16, ALp + go + 8);
        CPA16(ro + 20480,      BHp + go);
        CPA16(ro + 20480 + 16, BHp + go + 8);
        CPA16(ro + 30720,      BLp + go);
        CPA16(ro + 30720 + 16, BLp + go + 8);
        asm volatile("cp.async.commit_group;" ::: "memory");
    };

    float acc[2][8][4];
    #pragma unroll
    for (int mi = 0; mi < 2; ++mi)
        #pragma unroll
        for (int j = 0; j < 8; ++j)
            #pragma unroll
            for (int q = 0; q < 4; ++q) acc[mi][j][q] = 0.f;

    ldAB(0, 0);

    for (int kt = 0; kt < 16; ++kt) {
        int cur = kt & 1, nxt = cur ^ 1;
        if (kt + 1 < 16) {
            ldAB(nxt, kt + 1);
            asm volatile("cp.async.wait_group 1;" ::: "memory");
        } else {
            asm volatile("cp.async.wait_group 0;" ::: "memory");
        }
        __syncthreads();
        uint32_t abase = smb + cur * MG_STAGE;
        uint32_t bbase = abase + 20480;
        #pragma unroll
        for (int ks = 0; ks < 2; ++ks) {
            int kc = ks * 16;
            uint32_t ah[2][4], al[2][4], bh[4][4], bl[4][4];
            #pragma unroll
            for (int mi = 0; mi < 2; ++mi) {
                uint32_t ad = abase + (uint32_t)(wm * 32 + mi * 16 + a_row) * 80 + (kc + a_col) * 2;
                ldsm4(ah[mi], ad);
                ldsm4(al[mi], ad + 10240);
            }
            #pragma unroll
            for (int p = 0; p < 4; ++p) {
                uint32_t bd = bbase + (uint32_t)(wn * 64 + p * 16 + b_row) * 80 + (kc + b_col) * 2;
                ldsm4(bh[p], bd);
                ldsm4(bl[p], bd + 10240);
            }
            #pragma unroll
            for (int mi = 0; mi < 2; ++mi)
                #pragma unroll
                for (int j = 0; j < 8; ++j) {
                    const uint32_t* bhp = &bh[j >> 1][(j & 1) * 2];
                    const uint32_t* blp = &bl[j >> 1][(j & 1) * 2];
                    mma_bf16(acc[mi][j], ah[mi], bhp);
                    mma_bf16(acc[mi][j], al[mi], bhp);
                    mma_bf16(acc[mi][j], ah[mi], blp);
                }
        }
        __syncthreads();
    }

    if (omode == 1) {
        // stage tile in smem, then fully coalesced transposed stores
        float* smf = (float*)sm;   // [128][129]
        #pragma unroll
        for (int mi = 0; mi < 2; ++mi) {
            #pragma unroll
            for (int j = 0; j < 8; ++j) {
                int c0 = wn * 64 + j * 8 + (lane & 3) * 2;
                float b0 = bias[n0 + c0], b1 = bias[n0 + c0 + 1];
                #pragma unroll
                for (int half = 0; half < 2; ++half) {
                    int r = wm * 32 + mi * 16 + (lane >> 2) + half * 8;
                    smf[r * 129 + c0]     = acc[mi][j][half * 2 + 0] + b0;
                    smf[r * 129 + c0 + 1] = acc[mi][j][half * 2 + 1] + b1;
                }
            }
        }
        __syncthreads();
        #pragma unroll 4
        for (int i = 0; i < 64; ++i) {
            int idx = i * 256 + tid;        // 0..16383
            int cl = idx >> 7, rl = idx & 127;
            int row = m0 + rl;
            int b = row / Nspat, n = row - b * Nspat;
            Cf[((size_t)(b * Cc + n0 + cl)) * Nspat + n] = smf[rl * 129 + cl];
        }
        return;
    }

    #pragma unroll
    for (int mi = 0; mi < 2; ++mi) {
        int row0 = m0 + wm * 32 + mi * 16 + (lane >> 2);
        #pragma unroll
        for (int j = 0; j < 8; ++j) {
            int col0 = n0 + wn * 64 + j * 8 + (lane & 3) * 2;
            if (col0 >= Nc) continue;
            float b0 = bias[col0], b1 = bias[col0 + 1];
            #pragma unroll
            for (int half = 0; half < 2; ++half) {
                int row = row0 + half * 8;
                float v0 = acc[mi][j][half * 2 + 0] + b0;
                float v1 = acc[mi][j][half * 2 + 1] + b1;
                if (act == 1) { v0 = fmaxf(v0, 0.f); v1 = fmaxf(v1, 0.f); }
                if (act == 2) {
                    v0 = fminf(fmaxf(v0, -3.f), 3.f);
                    v1 = fminf(fmaxf(v1, -3.f), 3.f);
                }
                if (omode == 0) {
                    *(float2*)(Cf + (size_t)row * Nc + col0) = make_float2(v0, v1);
                } else {
                    uint32_t u0 = __float_as_uint(v0), u1 = __float_as_uint(v1);
                    uint32_t hp = __byte_perm(u0, u1, 0x7632);
                    float l0 = v0 - __uint_as_float(u0 & 0xFFFF0000u);
                    float l1 = v1 - __uint_as_float(u1 & 0xFFFF0000u);
                    __nv_bfloat162 lp = __float22bfloat162_rn(make_float2(l0, l1));
                    *(uint32_t*)(CH + (size_t)row * Nc + col0) = hp;
                    *(uint32_t*)(CL + (size_t)row * Nc + col0) = *(uint32_t*)&lp;
                }
            }
        }
    }
}

template<int ACT, int OMODE>
__global__ void __launch_bounds__(256, 2) k_sgemm(
    const __nv_bfloat16* __restrict__ AH, const __nv_bfloat16* __restrict__ AL,
    const __nv_bfloat16* __restrict__ BH, const __nv_bfloat16* __restrict__ BL,
    const float* __restrict__ bias,
    float* __restrict__ Cf, __nv_bfloat16* __restrict__ CH, __nv_bfloat16* __restrict__ CL,
    int Nc)
{
    extern __shared__ __align__(1024) char sm_dyn[];
    sgemm_body(AH, AL, BH, BL, bias, Cf, CH, CL, Nc, ACT, OMODE,
               blockIdx.y * 128, blockIdx.x * 128, sm_dyn);
}

// dual small GEMM: blocks [0,125) -> off=clip(hid@Wo2), [125,250) -> attn=Q@Wa
__global__ void __launch_bounds__(256, 2) k_sgemm_dual(
    const __nv_bfloat16* __restrict__ A1H, const __nv_bfloat16* __restrict__ A1L,
    const __nv_bfloat16* __restrict__ B1H, const __nv_bfloat16* __restrict__ B1L,
    const float* __restrict__ bias1, float* __restrict__ C1, int Nc1,
    const __nv_bfloat16* __restrict__ A2H, const __nv_bfloat16* __restrict__ A2L,
    const __nv_bfloat16* __restrict__ B2H, const __nv_bfloat16* __restrict__ B2L,
    const float* __restrict__ bias2, float* __restrict__ C2, int Nc2)
{
    extern __shared__ __align__(1024) char sm_dyn[];
    int by = blockIdx.y;
    if (by < 125)
        sgemm_body(A1H, A1L, B1H, B1L, bias1, C1, nullptr, nullptr, Nc1, 2, 0, by * 128, 0, sm_dyn);
    else
        sgemm_body(A2H, A2L, B2H, B2L, bias2, C2, nullptr, nullptr, Nc2, 0, 0, (by - 125) * 128, 0, sm_dyn);
}

// ---------------- merged weight prep ----------------
struct WPrepDesc {
    const float* W;
    __nv_bfloat16* H;
    __nv_bfloat16* L;
    int Ncols;
    int Npad;
};
__global__ void k_wprep_all(WPrepDesc w0, WPrepDesc w1, WPrepDesc w2, WPrepDesc w3, WPrepDesc w4) {
    WPrepDesc d;
    switch (blockIdx.z) {
        case 0: d = w0; break;
        case 1: d = w1; break;
        case 2: d = w2; break;
        case 3: d = w3; break;
        default: d = w4; break;
    }
    __shared__ float t[32][33];
    int k0 = blockIdx.y * 32, n0 = blockIdx.x * 32;
    if (n0 >= d.Npad) return;
    int tx = threadIdx.x, ty = threadIdx.y;  // (32,8)
    #pragma unroll
    for (int i = 0; i < 32; i += 8) {
        int k = k0 + ty + i, n = n0 + tx;
        t[ty + i][tx] = (n < d.Ncols) ? d.W[(size_t)k * d.Ncols + n] : 0.f;
    }
    __syncthreads();
    #pragma unroll
    for (int i = 0; i < 32; i += 8) {
        int n = n0 + ty + i, k = k0 + tx;
        float v = t[tx][ty + i];
        uint32_t b = __float_as_uint(v);
        float hv = __uint_as_float(b & 0xFFFF0000u);
        d.H[(size_t)n * 512 + k] = __ushort_as_bfloat16((unsigned short)(b >> 16));
        d.L[(size_t)n * 512 + k] = __float2bfloat16(v - hv);
    }
}

// ---------------- fused stats + transpose + LN -> split qH/qL ----------------
__global__ void __launch_bounds__(256) k_lnfuse(const float* __restrict__ fq,
                                                const float* __restrict__ lng,
                                                const float* __restrict__ lnb) {
    extern __shared__ __align__(1024) char sm_dyn[];
    float* sm = (float*)sm_dyn;
    float* smean = sm + 32 * 513;
    float* srstd = smean + 32;
    int b  = blockIdx.y;
    int n0 = blockIdx.x * 32;
    int tid = threadIdx.x;
    int warp = tid >> 5, lane = tid & 31;
    const float* src = fq + (size_t)b * Cc * Nspat + n0 + lane;
    #pragma unroll 8
    for (int it = 0; it < 64; ++it) {
        int c = it * 8 + warp;
        sm[lane * 513 + c] = src[(size_t)c * Nspat];
    }
    __syncthreads();
    #pragma unroll
    for (int i = 0; i < 4; ++i) {
        int tok = warp * 4 + i;
        float s = 0.f, ss = 0.f;
        const float* row = sm + tok * 513;
        #pragma unroll
        for (int j = 0; j < 16; ++j) {
            float v = row[lane + j * 32];
            s += v; ss += v * v;
        }
        #pragma unroll
        for (int o = 16; o > 0; o >>= 1) {
            s  += __shfl_xor_sync(0xffffffffu, s, o);
            ss += __shfl_xor_sync(0xffffffffu, ss, o);
        }
        if (lane == 0) {
            float mu = s * (1.f / Cc);
            float var = ss * (1.f / Cc) - mu * mu;
            smean[tok] = mu;
            srstd[tok] = rsqrtf(var + LN_EPS);
        }
    }
    __syncthreads();
    #pragma unroll
    for (int i = 0; i < 4; ++i) {
        int tok = warp * 4 + i;
        float mu = smean[tok], rs = srstd[tok];
        size_t obase = (size_t)(b * Nspat + n0 + tok) * Cc;
        const float* row = sm + tok * 513;
        #pragma unroll
        for (int k = 0; k < 4; ++k) {
            int c = lane * 4 + k * 128;
            float v0 = (row[c + 0] - mu) * rs * lng[c + 0] + lnb[c + 0];
            float v1 = (row[c + 1] - mu) * rs * lng[c + 1] + lnb[c + 1];
            float v2 = (row[c + 2] - mu) * rs * lng[c + 2] + lnb[c + 2];
            float v3 = (row[c + 3] - mu) * rs * lng[c + 3] + lnb[c + 3];
            uint32_t u0 = __float_as_uint(v0), u1 = __float_as_uint(v1);
            uint32_t u2 = __float_as_uint(v2), u3 = __float_as_uint(v3);
            uint2 hp = make_uint2(__byte_perm(u0, u1, 0x7632), __byte_perm(u2, u3, 0x7632));
            __nv_bfloat162 lp0 = __float22bfloat162_rn(make_float2(
                v0 - __uint_as_float(u0 & 0xFFFF0000u), v1 - __uint_as_float(u1 & 0xFFFF0000u)));
            __nv_bfloat162 lp1 = __float22bfloat162_rn(make_float2(
                v2 - __uint_as_float(u2 & 0xFFFF0000u), v3 - __uint_as_float(u3 & 0xFFFF0000u)));
            *(uint2*)(g_qH + obase + c) = hp;
            *(uint2*)(g_qL + obase + c) = make_uint2(*(uint32_t*)&lp0, *(uint32_t*)&lp1);
        }
    }
}

// ---------------- permute f_kv -> (B,NH,D,H,W,HD) as fp16 ----------------
__global__ void k_perm(const float* __restrict__ fkv) {
    __shared__ float s[HDc * 21];
    int blk = blockIdx.x;
    int x = blk % Dim;
    int y = (blk / Dim) % Dim;
    int h = (blk / (Dim * Dim)) % NHc;
    int b = blk / (Dim * Dim * NHc);
    const float* src = fkv + ((size_t)(b * Cc + h * HDc)) * Nspat + (y * Dim + x) * Dim;
    for (int idx = threadIdx.x; idx < HDc * Dim; idx += blockDim.x) {
        int hd = idx / Dim, z = idx - hd * Dim;
        s[hd * 21 + z] = src[(size_t)hd * Nspat + z];
    }
    __syncthreads();
    __half* dst = g_feats + ((size_t)(b * NHc + h) * Nspat) * HDc;
    for (int idx = threadIdx.x; idx < HDc * Dim; idx += blockDim.x) {
        int z = idx / HDc, hd = idx - z * HDc;
        dst[(size_t)((z * Dim + y) * Dim + x) * HDc + hd] = __float2half_rn(s[hd * 21 + z]);
    }
}

// ---------------- trilinear gather + fused softmax + weighted sum ----------------
// h-major warp mapping: all warps in a block share one head volume and walk
// neighboring tokens -> corner rows hit L1.
__global__ void k_sample() {
    int gw   = (blockIdx.x * blockDim.x + threadIdx.x) >> 5;
    int lane = threadIdx.x & 31;
    if (gw >= MTOT * NHc) return;
    int h = gw / MTOT;
    int t = gw - h * MTOT;
    int b = t / Nspat;
    int n = t - b * Nspat;
    int y = n / (Dim * Dim);
    int x = (n / Dim) % Dim;
    int z = n % Dim;
    int gidx = t * NHc + h;   // layout of g_off / g_attn

    const float* off = g_off + (size_t)gidx * NPc * 3;
    float4 lg = ((const float4*)g_attn)[gidx];
    float mx = fmaxf(fmaxf(lg.x, lg.y), fmaxf(lg.z, lg.w));
    float e0 = __expf(lg.x - mx), e1 = __expf(lg.y - mx);
    float e2 = __expf(lg.z - mx), e3 = __expf(lg.w - mx);
    float inv = 1.f / (e0 + e1 + e2 + e3);
    float aw[4] = {e0 * inv, e1 * inv, e2 * inv, e3 * inv};

    const __half* feats = g_feats + ((size_t)(b * NHc + h) * Nspat) * HDc;

    float acc0 = 0.f, acc1 = 0.f;
    #pragma unroll
    for (int p = 0; p < NPc; ++p) {
        float ap = aw[p];
        float ix = fminf(fmaxf((float)y + off[p * 3 + 0], 0.f), (float)(Dim - 1));
        float iy = fminf(fmaxf((float)x + off[p * 3 + 1], 0.f), (float)(Dim - 1));
        float iz = fminf(fmaxf((float)z + off[p * 3 + 2], 0.f), (float)(Dim - 1));
        float x0f = floorf(ix), y0f = floorf(iy), z0f = floorf(iz);
        float fx = ix - x0f, fy = iy - y0f, fz = iz - z0f;
        int x0 = (int)x0f, y0 = (int)y0f, z0 = (int)z0f;
        int x1 = min(x0 + 1, Dim - 1);
        int y1 = min(y0 + 1, Dim - 1);
        int z1 = min(z0 + 1, Dim - 1);
        float wx[2] = {1.f - fx, fx};
        float wy[2] = {1.f - fy, fy};
        float wz[2] = {1.f - fz, fz};
        int   xs[2] = {x0, x1}, ys[2] = {y0, y1}, zs[2] = {z0, z1};
        #pragma unroll
        for (int dz = 0; dz < 2; ++dz)
            #pragma unroll
            for (int dy = 0; dy < 2; ++dy)
                #pragma unroll
                for (int dx = 0; dx < 2; ++dx) {
                    float w = ap * wz[dz] * wy[dy] * wx[dx];
                    const __half2* f = (const __half2*)(feats + (size_t)((zs[dz] * Dim + ys[dy]) * Dim + xs[dx]) * HDc);
                    float2 v = __half22float2(f[lane]);
                    acc0 += w * v.x;
                    acc1 += w * v.y;
                }
    }
    size_t oidx = (size_t)t * Cc + h * HDc + lane * 2;
    uint32_t u0 = __float_as_uint(acc0), u1 = __float_as_uint(acc1);
    uint32_t hp = __byte_perm(u0, u1, 0x7632);
    __nv_bfloat162 lp = __float22bfloat162_rn(make_float2(
        acc0 - __uint_as_float(u0 & 0xFFFF0000u), acc1 - __uint_as_float(u1 & 0xFFFF0000u)));
    *(uint32_t*)(g_sH + oidx) = hp;
    *(uint32_t*)(g_sL + oidx) = *(uint32_t*)&lp;
}

// ---------------- host ----------------
extern "C" void kernel_launch(void* const* d_in, const int* in_sizes, int n_in,
                              void* d_out, int out_size) {
    (void)in_sizes; (void)n_in; (void)out_size;
    const float* f_query = (const float*)d_in[0];
    const float* f_kv    = (const float*)d_in[1];
    const float* ln_g    = (const float*)d_in[2];
    const float* ln_b    = (const float*)d_in[3];
    const float* Wq   = (const float*)d_in[4];
    const float* bq   = (const float*)d_in[5];
    const float* Wo1  = (const float*)d_in[6];
    const float* bo1  = (const float*)d_in[7];
    const float* Wo2  = (const float*)d_in[8];
    const float* bo2  = (const float*)d_in[9];
    const float* Wa   = (const float*)d_in[10];
    const float* ba   = (const float*)d_in[11];
    const float* Wout = (const float*)d_in[12];
    const float* bout = (const float*)d_in[13];
    float* out = (float*)d_out;

    float *p_off, *p_attn;
    cudaGetSymbolAddress((void**)&p_off,  g_off);
    cudaGetSymbolAddress((void**)&p_attn, g_attn);
    __nv_bfloat16 *qH, *qL, *QH, *QL, *hH, *hL, *sH, *sL;
    cudaGetSymbolAddress((void**)&qH, g_qH);   cudaGetSymbolAddress((void**)&qL, g_qL);
    cudaGetSymbolAddress((void**)&QH, g_QH);   cudaGetSymbolAddress((void**)&QL, g_QL);
    cudaGetSymbolAddress((void**)&hH, g_hidH); cudaGetSymbolAddress((void**)&hL, g_hidL);
    cudaGetSymbolAddress((void**)&sH, g_sH);   cudaGetSymbolAddress((void**)&sL, g_sL);
    __nv_bfloat16 *wqH, *wqL, *wo1H, *wo1L, *wo2H, *wo2L, *waH, *waL, *woH, *woL;
    cudaGetSymbolAddress((void**)&wqH,  g_WqH);   cudaGetSymbolAddress((void**)&wqL,  g_WqL);
    cudaGetSymbolAddress((void**)&wo1H, g_Wo1H);  cudaGetSymbolAddress((void**)&wo1L, g_Wo1L);
    cudaGetSymbolAddress((void**)&wo2H, g_Wo2H);  cudaGetSymbolAddress((void**)&wo2L, g_Wo2L);
    cudaGetSymbolAddress((void**)&waH,  g_WaH);   cudaGetSymbolAddress((void**)&waL,  g_WaL);
    cudaGetSymbolAddress((void**)&woH,  g_WoutH); cudaGetSymbolAddress((void**)&woL,  g_WoutL);

    cudaFuncSetAttribute(k_sgemm<0,2>, cudaFuncAttributeMaxDynamicSharedMemorySize, MG_SMEM);
    cudaFuncSetAttribute(k_sgemm<1,2>, cudaFuncAttributeMaxDynamicSharedMemorySize, MG_SMEM);
    cudaFuncSetAttribute(k_sgemm<0,1>, cudaFuncAttributeMaxDynamicSharedMemorySize, MG_SMEM);
    cudaFuncSetAttribute(k_sgemm_dual, cudaFuncAttributeMaxDynamicSharedMemorySize, MG_SMEM);
    const int LN_SMEM = (32 * 513 + 64) * 4;
    cudaFuncSetAttribute(k_lnfuse, cudaFuncAttributeMaxDynamicSharedMemorySize, LN_SMEM);

    // merged weight prep (transpose + split) — one launch
    WPrepDesc w0{Wq,   wqH,  wqL,  512, 512};
    WPrepDesc w1{Wo1,  wo1H, wo1L, 512, 512};
    WPrepDesc w2{Wout, woH,  woL,  512, 512};
    WPrepDesc w3{Wo2,  wo2H, wo2L, NHc * NPc * 3, 128};
    WPrepDesc w4{Wa,   waH,  waL,  NHc * NPc, 128};
    k_wprep_all<<<dim3(16, 16, 5), dim3(32, 8)>>>(w0, w1, w2, w3, w4);

    // fused stats + transpose + LN -> split q
    k_lnfuse<<<dim3(250, Bc), 256, LN_SMEM>>>(f_query, ln_g, ln_b);
    // permute KV to fp16 channels-last
    k_perm<<<Bc * NHc * Dim * Dim, 256>>>(f_kv);
    // Q = q @ Wq + bq  -> split
    k_sgemm<0,2><<<dim3(4, 125), 256, MG_SMEM>>>(qH, qL, wqH, wqL, bq, nullptr, QH, QL, Cc);
    // hid = relu(Q @ Wo1 + bo1) -> split
    k_sgemm<1,2><<<dim3(4, 125), 256, MG_SMEM>>>(QH, QL, wo1H, wo1L, bo1, nullptr, hH, hL, Cc);
    // off = clip(hid @ Wo2 + bo2) AND attn logits = Q @ Wa + ba (one wave)
    k_sgemm_dual<<<dim3(1, 250), 256, MG_SMEM>>>(hH, hL, wo2H, wo2L, bo2, p_off, NHc * NPc * 3,
                                                 QH, QL, waH,  waL,  ba,  p_attn, NHc * NPc);
    // sampling (softmax fused, h-major locality) -> split samp
    k_sample<<<(MTOT * NHc) * 32 / 256, 256>>>();
    // out = samp @ Wout + bout, transposed coalesced store
    k_sgemm<0,1><<<dim3(4, 125), 256, MG_SMEM>>>(sH, sL, woH, woL, bout, out, nullptr, nullptr, Cc);
}

// round 8
// speedup vs baseline: 1.1175x; 1.1175x over previous
#include <cuda_runtime.h>
#include <cuda_bf16.h>
#include <cuda_fp16.h>
#include <cstdint>

#define Bc 2
#define Cc 512
#define NHc 8
#define NPc 4
#define HDc 64
#define Dim 20
#define Nspat 8000          // 20*20*20
#define MTOT (Bc*Nspat)     // 16000
#define LN_EPS 1e-5f

// ---------------- scratch (no allocations allowed) ----------------
__device__ __align__(16) __nv_bfloat16 g_qH  [(size_t)MTOT*Cc];
__device__ __align__(16) __nv_bfloat16 g_qL  [(size_t)MTOT*Cc];
__device__ __align__(16) __nv_bfloat16 g_hidH[(size_t)MTOT*Cc];
__device__ __align__(16) __nv_bfloat16 g_hidL[(size_t)MTOT*Cc];
__device__ __align__(16) __nv_bfloat16 g_sH  [(size_t)MTOT*Cc];
__device__ __align__(16) __nv_bfloat16 g_sL  [(size_t)MTOT*Cc];
__device__ __align__(16) float g_off [(size_t)MTOT*NHc*NPc*3];
__device__ __align__(16) float g_attn[(size_t)MTOT*NHc*NPc];
__device__ __align__(16) __half g_feats[(size_t)Bc*NHc*Nspat*HDc];
// weight-prep buffers
__device__ __align__(256) __nv_bfloat16 g_WqNH [512*512];   // Wq non-transposed split (B of product)
__device__ __align__(256) __nv_bfloat16 g_WqNL [512*512];
__device__ __align__(256) __nv_bfloat16 g_BcatH[640*512];   // [Wo1T(512); WaT(128)] split (A of product)
__device__ __align__(256) __nv_bfloat16 g_BcatL[640*512];
__device__ __align__(256) __nv_bfloat16 g_W1H  [640*512];   // B' = Bcat @ WqN, split (B of merged GEMM)
__device__ __align__(256) __nv_bfloat16 g_W1L  [640*512];
__device__ __align__(256) __nv_bfloat16 g_Wo2H [128*512];
__device__ __align__(256) __nv_bfloat16 g_Wo2L [128*512];
__device__ __align__(256) __nv_bfloat16 g_WoutH[512*512];
__device__ __align__(256) __nv_bfloat16 g_WoutL[512*512];
__device__ float g_bc[640];       // merged bias [b1'(512); ba'(32); 0]
__device__ float g_bzero[512];    // zero bias (static zero-init)

// ================= helpers =================
__device__ __forceinline__ uint32_t smem_u32(const void* p) {
    uint32_t a;
    asm("{ .reg .u64 t; cvta.to.shared.u64 t, %1; cvt.u32.u64 %0, t; }" : "=r"(a) : "l"(p));
    return a;
}
__device__ __forceinline__ void ldsm4(uint32_t* r, uint32_t addr) {
    asm volatile("ldmatrix.sync.aligned.m8n8.x4.shared.b16 {%0,%1,%2,%3}, [%4];"
        : "=r"(r[0]), "=r"(r[1]), "=r"(r[2]), "=r"(r[3]) : "r"(addr));
}
__device__ __forceinline__ void mma_bf16(float* c, const uint32_t* a, const uint32_t* b) {
    asm volatile(
        "mma.sync.aligned.m16n8k16.row.col.f32.bf16.bf16.f32 "
        "{%0,%1,%2,%3}, {%4,%5,%6,%7}, {%8,%9}, {%0,%1,%2,%3};"
        : "+f"(c[0]), "+f"(c[1]), "+f"(c[2]), "+f"(c[3])
        : "r"(a[0]), "r"(a[1]), "r"(a[2]), "r"(a[3]), "r"(b[0]), "r"(b[1]));
}
#define CPA16(dst, src) \
    asm volatile("cp.async.cg.shared.global [%0], [%1], 16;" :: "r"(dst), "l"(src) : "memory")

// ================= split-bf16 HMMA GEMM (all operands pre-split) =================
// Tile 128x128, BK=32, 2-stage cp.async pipeline. 3 MMAs: hh + lh + hl.
#define MG_STAGE 40960
#define MG_SMEM  (2*MG_STAGE)   // 80KB dynamic

// omode: 0 = fp32 row-major, 1 = fp32 transposed (B,C,Nspat) scattered,
//        2 = split bf16 H/L, 3 = merged: col<512 relu+split hid, 512<=col<544 fp32 attn
__device__ __forceinline__ void sgemm_body(
    const __nv_bfloat16* __restrict__ AH, const __nv_bfloat16* __restrict__ AL,
    const __nv_bfloat16* __restrict__ BH, const __nv_bfloat16* __restrict__ BL,
    const float* __restrict__ bias,
    float* __restrict__ Cf, __nv_bfloat16* __restrict__ CH, __nv_bfloat16* __restrict__ CL,
    int Nc, int act, int omode, int m0, int n0, char* sm)
{
    const uint32_t smb = smem_u32(sm);
    const int tid = threadIdx.x;
    const int wid = tid >> 5, lane = tid & 31;
    const int wm = wid >> 1;
    const int wn = wid & 1;

    const int tq = lane >> 3, rr = lane & 7;
    const int a_row = rr + (tq & 1) * 8;
    const int a_col = (tq >> 1) * 8;
    const int b_row = rr + (tq >> 1) * 8;
    const int b_col = (tq & 1) * 8;

    const int r2  = tid >> 1;            // 0..127
    const int kc2 = (tid & 1) * 32;      // byte offset: 0 or 32

    const __nv_bfloat16* AHp = AH + (size_t)(m0 + r2) * 512 + (tid & 1) * 16;
    const __nv_bfloat16* ALp = AL + (size_t)(m0 + r2) * 512 + (tid & 1) * 16;
    const __nv_bfloat16* BHp = BH + (size_t)(n0 + r2) * 512 + (tid & 1) * 16;
    const __nv_bfloat16* BLp = BL + (size_t)(n0 + r2) * 512 + (tid & 1) * 16;

    auto ldAB = [&](int stage, int kt) {
        uint32_t ro = smb + stage * MG_STAGE + r2 * 80 + kc2;
        const int go = kt * 32;
        CPA16(ro,              AHp + go);
        CPA16(ro + 16,         AHp + go + 8);
        CPA16(ro + 10240,      ALp + go);
        CPA16(ro + 10240 + 16, ALp + go + 8);
        CPA16(ro + 20480,      BHp + go);
        CPA16(ro + 20480 + 16, BHp + go + 8);
        CPA16(ro + 30720,      BLp + go);
        CPA16(ro + 30720 + 16, BLp + go + 8);
        asm volatile("cp.async.commit_group;" ::: "memory");
    };

    float acc[2][8][4];
    #pragma unroll
    for (int mi = 0; mi < 2; ++mi)
        #pragma unroll
        for (int j = 0; j < 8; ++j)
            #pragma unroll
            for (int q = 0; q < 4; ++q) acc[mi][j][q] = 0.f;

    ldAB(0, 0);

    for (int kt = 0; kt < 16; ++kt) {
        int cur = kt & 1, nxt = cur ^ 1;
        if (kt + 1 < 16) {
            ldAB(nxt, kt + 1);
            asm volatile("cp.async.wait_group 1;" ::: "memory");
        } else {
            asm volatile("cp.async.wait_group 0;" ::: "memory");
        }
        __syncthreads();
        uint32_t abase = smb + cur * MG_STAGE;
        uint32_t bbase = abase + 20480;
        #pragma unroll
        for (int ks = 0; ks < 2; ++ks) {
            int kc = ks * 16;
            uint32_t ah[2][4], al[2][4], bh[4][4], bl[4][4];
            #pragma unroll
            for (int mi = 0; mi < 2; ++mi) {
                uint32_t ad = abase + (uint32_t)(wm * 32 + mi * 16 + a_row) * 80 + (kc + a_col) * 2;
                ldsm4(ah[mi], ad);
                ldsm4(al[mi], ad + 10240);
            }
            #pragma unroll
            for (int p = 0; p < 4; ++p) {
                uint32_t bd = bbase + (uint32_t)(wn * 64 + p * 16 + b_row) * 80 + (kc + b_col) * 2;
                ldsm4(bh[p], bd);
                ldsm4(bl[p], bd + 10240);
            }
            #pragma unroll
            for (int mi = 0; mi < 2; ++mi)
                #pragma unroll
                for (int j = 0; j < 8; ++j) {
                    const uint32_t* bhp = &bh[j >> 1][(j & 1) * 2];
                    const uint32_t* blp = &bl[j >> 1][(j & 1) * 2];
                    mma_bf16(acc[mi][j], ah[mi], bhp);
                    mma_bf16(acc[mi][j], al[mi], bhp);
                    mma_bf16(acc[mi][j], ah[mi], blp);
                }
        }
        __syncthreads();
    }

    #pragma unroll
    for (int mi = 0; mi < 2; ++mi) {
        int row0 = m0 + wm * 32 + mi * 16 + (lane >> 2);
        #pragma unroll
        for (int j = 0; j < 8; ++j) {
            int col0 = n0 + wn * 64 + j * 8 + (lane & 3) * 2;
            if (col0 >= Nc) continue;
            float b0 = bias[col0], b1 = bias[col0 + 1];
            #pragma unroll
            for (int half = 0; half < 2; ++half) {
                int row = row0 + half * 8;
                float v0 = acc[mi][j][half * 2 + 0] + b0;
                float v1 = acc[mi][j][half * 2 + 1] + b1;
                if (omode == 3) {
                    if (col0 < 512) {
                        v0 = fmaxf(v0, 0.f); v1 = fmaxf(v1, 0.f);
                        uint32_t u0 = __float_as_uint(v0), u1 = __float_as_uint(v1);
                        uint32_t hp = __byte_perm(u0, u1, 0x7632);
                        float l0 = v0 - __uint_as_float(u0 & 0xFFFF0000u);
                        float l1 = v1 - __uint_as_float(u1 & 0xFFFF0000u);
                        __nv_bfloat162 lp = __float22bfloat162_rn(make_float2(l0, l1));
                        *(uint32_t*)(CH + (size_t)row * 512 + col0) = hp;
                        *(uint32_t*)(CL + (size_t)row * 512 + col0) = *(uint32_t*)&lp;
                    } else {
                        *(float2*)(Cf + (size_t)row * 32 + (col0 - 512)) = make_float2(v0, v1);
                    }
                    continue;
                }
                if (act == 1) { v0 = fmaxf(v0, 0.f); v1 = fmaxf(v1, 0.f); }
                if (act == 2) {
                    v0 = fminf(fmaxf(v0, -3.f), 3.f);
                    v1 = fminf(fmaxf(v1, -3.f), 3.f);
                }
                if (omode == 0) {
                    *(float2*)(Cf + (size_t)row * Nc + col0) = make_float2(v0, v1);
                } else if (omode == 1) {
                    int b = row / Nspat, n = row - b * Nspat;
                    Cf[((size_t)(b * Cc + col0)) * Nspat + n] = v0;
                    Cf[((size_t)(b * Cc + col0 + 1)) * Nspat + n] = v1;
                } else {
                    uint32_t u0 = __float_as_uint(v0), u1 = __float_as_uint(v1);
                    uint32_t hp = __byte_perm(u0, u1, 0x7632);
                    float l0 = v0 - __uint_as_float(u0 & 0xFFFF0000u);
                    float l1 = v1 - __uint_as_float(u1 & 0xFFFF0000u);
                    __nv_bfloat162 lp = __float22bfloat162_rn(make_float2(l0, l1));
                    *(uint32_t*)(CH + (size_t)row * Nc + col0) = hp;
                    *(uint32_t*)(CL + (size_t)row * Nc + col0) = *(uint32_t*)&lp;
                }
            }
        }
    }
}

template<int ACT, int OMODE>
__global__ void __launch_bounds__(256, 2) k_sgemm(
    const __nv_bfloat16* __restrict__ AH, const __nv_bfloat16* __restrict__ AL,
    const __nv_bfloat16* __restrict__ BH, const __nv_bfloat16* __restrict__ BL,
    const float* __restrict__ bias,
    float* __restrict__ Cf, __nv_bfloat16* __restrict__ CH, __nv_bfloat16* __restrict__ CL,
    int Nc)
{
    extern __shared__ __align__(1024) char sm_dyn[];
    sgemm_body(AH, AL, BH, BL, bias, Cf, CH, CL, Nc, ACT, OMODE,
               blockIdx.y * 128, blockIdx.x * 128, sm_dyn);
}

// ---------------- merged weight prep (transpose+split or copy+split) ----------------
struct WPrepDesc {
    const float* W;
    __nv_bfloat16* H;
    __nv_bfloat16* L;
    int Ncols;   // columns of W
    int Npad;    // output rows (transpose mode)
    int trans;   // 1 = transpose, 0 = direct copy
};
__global__ void k_wprep_all(WPrepDesc w0, WPrepDesc w1, WPrepDesc w2, WPrepDesc w3, WPrepDesc w4) {
    WPrepDesc d;
    switch (blockIdx.z) {
        case 0: d = w0; break;
        case 1: d = w1; break;
        case 2: d = w2; break;
        case 3: d = w3; break;
        default: d = w4; break;
    }
    int tx = threadIdx.x, ty = threadIdx.y;  // (32,8)
    if (!d.trans) {
        // direct: H[k][j] = split(W[k][j]); W is 512 x Ncols(=512)
        int k0 = blockIdx.y * 32, j0 = blockIdx.x * 32;
        #pragma unroll
        for (int i = 0; i < 32; i += 8) {
            int k = k0 + ty + i, j = j0 + tx;
            float v = d.W[(size_t)k * d.Ncols + j];
            uint32_t b = __float_as_uint(v);
            d.H[(size_t)k * 512 + j] = __ushort_as_bfloat16((unsigned short)(b >> 16));
            d.L[(size_t)k * 512 + j] = __float2bfloat16(v - __uint_as_float(b & 0xFFFF0000u));
        }
        return;
    }
    __shared__ float t[32][33];
    int k0 = blockIdx.y * 32, n0 = blockIdx.x * 32;
    if (n0 >= d.Npad) return;
    #pragma unroll
    for (int i = 0; i < 32; i += 8) {
        int k = k0 + ty + i, n = n0 + tx;
        t[ty + i][tx] = (n < d.Ncols) ? d.W[(size_t)k * d.Ncols + n] : 0.f;
    }
    __syncthreads();
    #pragma unroll
    for (int i = 0; i < 32; i += 8) {
        int n = n0 + ty + i, k = k0 + tx;
        float v = t[tx][ty + i];
        uint32_t b = __float_as_uint(v);
        float hv = __uint_as_float(b & 0xFFFF0000u);
        d.H[(size_t)n * 512 + k] = __ushort_as_bfloat16((unsigned short)(b >> 16));
        d.L[(size_t)n * 512 + k] = __float2bfloat16(v - hv);
    }
}

// ---------------- bias prep: bc = [bq@Wo1+bo1 (512); bq@Wa+ba (32); 0 (96)] ----------------
__global__ void k_bprep(const float* __restrict__ bq,
                        const float* __restrict__ Wo1, const float* __restrict__ bo1,
                        const float* __restrict__ Wa,  const float* __restrict__ ba) {
    int n = blockIdx.x * 128 + threadIdx.x;
    if (n >= 640) return;
    float s = 0.f;
    if (n < 512) {
        s = bo1[n];
        for (int j = 0; j < 512; ++j) s += bq[j] * Wo1[(size_t)j * 512 + n];
    } else if (n < 544) {
        int c = n - 512;
        s = ba[c];
        for (int j = 0; j < 512; ++j) s += bq[j] * Wa[(size_t)j * 32 + c];
    }
    g_bc[n] = s;
}

// ---------------- fused stats + transpose + LN -> split qH/qL ----------------
__global__ void __launch_bounds__(256) k_lnfuse(const float* __restrict__ fq,
                                                const float* __restrict__ lng,
                                                const float* __restrict__ lnb) {
    extern __shared__ __align__(1024) char sm_dyn[];
    float* sm = (float*)sm_dyn;
    float* smean = sm + 32 * 513;
    float* srstd = smean + 32;
    int b  = blockIdx.y;
    int n0 = blockIdx.x * 32;
    int tid = threadIdx.x;
    int warp = tid >> 5, lane = tid & 31;
    const float* src = fq + (size_t)b * Cc * Nspat + n0 + lane;
    #pragma unroll 8
    for (int it = 0; it < 64; ++it) {
        int c = it * 8 + warp;
        sm[lane * 513 + c] = src[(size_t)c * Nspat];
    }
    __syncthreads();
    #pragma unroll
    for (int i = 0; i < 4; ++i) {
        int tok = warp * 4 + i;
        float s = 0.f, ss = 0.f;
        const float* row = sm + tok * 513;
        #pragma unroll
        for (int j = 0; j < 16; ++j) {
            float v = row[lane + j * 32];
            s += v; ss += v * v;
        }
        #pragma unroll
        for (int o = 16; o > 0; o >>= 1) {
            s  += __shfl_xor_sync(0xffffffffu, s, o);
            ss += __shfl_xor_sync(0xffffffffu, ss, o);
        }
        if (lane == 0) {
            float mu = s * (1.f / Cc);
            float var = ss * (1.f / Cc) - mu * mu;
            smean[tok] = mu;
            srstd[tok] = rsqrtf(var + LN_EPS);
        }
    }
    __syncthreads();
    #pragma unroll
    for (int i = 0; i < 4; ++i) {
        int tok = warp * 4 + i;
        float mu = smean[tok], rs = srstd[tok];
        size_t obase = (size_t)(b * Nspat + n0 + tok) * Cc;
        const float* row = sm + tok * 513;
        #pragma unroll
        for (int k = 0; k < 4; ++k) {
            int c = lane * 4 + k * 128;
            float v0 = (row[c + 0] - mu) * rs * lng[c + 0] + lnb[c + 0];
            float v1 = (row[c + 1] - mu) * rs * lng[c + 1] + lnb[c + 1];
            float v2 = (row[c + 2] - mu) * rs * lng[c + 2] + lnb[c + 2];
            float v3 = (row[c + 3] - mu) * rs * lng[c + 3] + lnb[c + 3];
            uint32_t u0 = __float_as_uint(v0), u1 = __float_as_uint(v1);
            uint32_t u2 = __float_as_uint(v2), u3 = __float_as_uint(v3);
            uint2 hp = make_uint2(__byte_perm(u0, u1, 0x7632), __byte_perm(u2, u3, 0x7632));
            __nv_bfloat162 lp0 = __float22bfloat162_rn(make_float2(
                v0 - __uint_as_float(u0 & 0xFFFF0000u), v1 - __uint_as_float(u1 & 0xFFFF0000u)));
            __nv_bfloat162 lp1 = __float22bfloat162_rn(make_float2(
                v2 - __uint_as_float(u2 & 0xFFFF0000u), v3 - __uint_as_float(u3 & 0xFFFF0000u)));
            *(uint2*)(g_qH + obase + c) = hp;
            *(uint2*)(g_qL + obase + c) = make_uint2(*(uint32_t*)&lp0, *(uint32_t*)&lp1);
        }
    }
}

// ---------------- permute f_kv -> (B,NH,D,H,W,HD) as fp16 ----------------
__global__ void k_perm(const float* __restrict__ fkv) {
    __shared__ float s[HDc * 21];
    int blk = blockIdx.x;
    int x = blk % Dim;
    int y = (blk / Dim) % Dim;
    int h = (blk / (Dim * Dim)) % NHc;
    int b = blk / (Dim * Dim * NHc);
    const float* src = fkv + ((size_t)(b * Cc + h * HDc)) * Nspat + (y * Dim + x) * Dim;
    for (int idx = threadIdx.x; idx < HDc * Dim; idx += blockDim.x) {
        int hd = idx / Dim, z = idx - hd * Dim;
        s[hd * 21 + z] = src[(size_t)hd * Nspat + z];
    }
    __syncthreads();
    __half* dst = g_feats + ((size_t)(b * NHc + h) * Nspat) * HDc;
    for (int idx = threadIdx.x; idx < HDc * Dim; idx += blockDim.x) {
        int z = idx / HDc, hd = idx - z * HDc;
        dst[(size_t)((z * Dim + y) * Dim + x) * HDc + hd] = __float2half_rn(s[hd * 21 + z]);
    }
}

// ---------------- trilinear gather + fused softmax + weighted sum ----------------
__global__ void k_sample() {
    int gw   = (blockIdx.x * blockDim.x + threadIdx.x) >> 5;
    int lane = threadIdx.x & 31;
    if (gw >= MTOT * NHc) return;
    int h = gw % NHc;
    int t = gw / NHc;
    int b = t / Nspat;
    int n = t - b * Nspat;
    int y = n / (Dim * Dim);
    int x = (n / Dim) % Dim;
    int z = n % Dim;

    const float* off = g_off + (size_t)gw * NPc * 3;
    float4 lg = ((const float4*)g_attn)[gw];
    float mx = fmaxf(fmaxf(lg.x, lg.y), fmaxf(lg.z, lg.w));
    float e0 = __expf(lg.x - mx), e1 = __expf(lg.y - mx);
    float e2 = __expf(lg.z - mx), e3 = __expf(lg.w - mx);
    float inv = 1.f / (e0 + e1 + e2 + e3);
    float aw[4] = {e0 * inv, e1 * inv, e2 * inv, e3 * inv};

    const __half* feats = g_feats + ((size_t)(b * NHc + h) * Nspat) * HDc;

    float acc0 = 0.f, acc1 = 0.f;
    #pragma unroll
    for (int p = 0; p < NPc; ++p) {
        float ap = aw[p];
        float ix = fminf(fmaxf((float)y + off[p * 3 + 0], 0.f), (float)(Dim - 1));
        float iy = fminf(fmaxf((float)x + off[p * 3 + 1], 0.f), (float)(Dim - 1));
        float iz = fminf(fmaxf((float)z + off[p * 3 + 2], 0.f), (float)(Dim - 1));
        float x0f = floorf(ix), y0f = floorf(iy), z0f = floorf(iz);
        float fx = ix - x0f, fy = iy - y0f, fz = iz - z0f;
        int x0 = (int)x0f, y0 = (int)y0f, z0 = (int)z0f;
        int x1 = min(x0 + 1, Dim - 1);
        int y1 = min(y0 + 1, Dim - 1);
        int z1 = min(z0 + 1, Dim - 1);
        float wx[2] = {1.f - fx, fx};
        float wy[2] = {1.f - fy, fy};
        float wz[2] = {1.f - fz, fz};
        int   xs[2] = {x0, x1}, ys[2] = {y0, y1}, zs[2] = {z0, z1};
        #pragma unroll
        for (int dz = 0; dz < 2; ++dz)
            #pragma unroll
            for (int dy = 0; dy < 2; ++dy)
                #pragma unroll
                for (int dx = 0; dx < 2; ++dx) {
                    float w = ap * wz[dz] * wy[dy] * wx[dx];
                    const __half2* f = (const __half2*)(feats + (size_t)((zs[dz] * Dim + ys[dy]) * Dim + xs[dx]) * HDc);
                    float2 v = __half22float2(f[lane]);
                    acc0 += w * v.x;
                    acc1 += w * v.y;
                }
    }
    size_t oidx = (size_t)t * Cc + h * HDc + lane * 2;
    uint32_t u0 = __float_as_uint(acc0), u1 = __float_as_uint(acc1);
    uint32_t hp = __byte_perm(u0, u1, 0x7632);
    __nv_bfloat162 lp = __float22bfloat162_rn(make_float2(
        acc0 - __uint_as_float(u0 & 0xFFFF0000u), acc1 - __uint_as_float(u1 & 0xFFFF0000u)));
    *(uint32_t*)(g_sH + oidx) = hp;
    *(uint32_t*)(g_sL + oidx) = *(uint32_t*)&lp;
}

// ---------------- host ----------------
extern "C" void kernel_launch(void* const* d_in, const int* in_sizes, int n_in,
                              void* d_out, int out_size) {
    (void)in_sizes; (void)n_in; (void)out_size;
    const float* f_query = (const float*)d_in[0];
    const float* f_kv    = (const float*)d_in[1];
    const float* ln_g    = (const float*)d_in[2];
    const float* ln_b    = (const float*)d_in[3];
    const float* Wq   = (const float*)d_in[4];
    const float* bq   = (const float*)d_in[5];
    const float* Wo1  = (const float*)d_in[6];
    const float* bo1  = (const float*)d_in[7];
    const float* Wo2  = (const float*)d_in[8];
    const float* bo2  = (const float*)d_in[9];
    const float* Wa   = (const float*)d_in[10];
    const float* ba   = (const float*)d_in[11];
    const float* Wout = (const float*)d_in[12];
    const float* bout = (const float*)d_in[13];
    float* out = (float*)d_out;

    float *p_off, *p_attn, *p_bc, *p_bz;
    cudaGetSymbolAddress((void**)&p_off,  g_off);
    cudaGetSymbolAddress((void**)&p_attn, g_attn);
    cudaGetSymbolAddress((void**)&p_bc,   g_bc);
    cudaGetSymbolAddress((void**)&p_bz,   g_bzero);
    __nv_bfloat16 *qH, *qL, *hH, *hL, *sH, *sL;
    cudaGetSymbolAddress((void**)&qH, g_qH);   cudaGetSymbolAddress((void**)&qL, g_qL);
    cudaGetSymbolAddress((void**)&hH, g_hidH); cudaGetSymbolAddress((void**)&hL, g_hidL);
    cudaGetSymbolAddress((void**)&sH, g_sH);   cudaGetSymbolAddress((void**)&sL, g_sL);
    __nv_bfloat16 *wqnH, *wqnL, *bcH, *bcL, *w1H, *w1L, *wo2H, *wo2L, *woH, *woL;
    cudaGetSymbolAddress((void**)&wqnH, g_WqNH); cudaGetSymbolAddress((void**)&wqnL, g_WqNL);
    cudaGetSymbolAddress((void**)&bcH,  g_BcatH); cudaGetSymbolAddress((void**)&bcL,  g_BcatL);
    cudaGetSymbolAddress((void**)&w1H,  g_W1H);  cudaGetSymbolAddress((void**)&w1L,  g_W1L);
    cudaGetSymbolAddress((void**)&wo2H, g_Wo2H); cudaGetSymbolAddress((void**)&wo2L, g_Wo2L);
    cudaGetSymbolAddress((void**)&woH,  g_WoutH); cudaGetSymbolAddress((void**)&woL,  g_WoutL);

    cudaFuncSetAttribute(k_sgemm<0,2>, cudaFuncAttributeMaxDynamicSharedMemorySize, MG_SMEM);
    cudaFuncSetAttribute(k_sgemm<1,3>, cudaFuncAttributeMaxDynamicSharedMemorySize, MG_SMEM);
    cudaFuncSetAttribute(k_sgemm<2,0>, cudaFuncAttributeMaxDynamicSharedMemorySize, MG_SMEM);
    cudaFuncSetAttribute(k_sgemm<0,1>, cudaFuncAttributeMaxDynamicSharedMemorySize, MG_SMEM);
    const int LN_SMEM = (32 * 513 + 64) * 4;
    cudaFuncSetAttribute(k_lnfuse, cudaFuncAttributeMaxDynamicSharedMemorySize, LN_SMEM);

    // weight prep: WqN direct-split; [Wo1T;WaT] into Bcat; Wo2T; WoutT
    WPrepDesc d0{Wq,   wqnH, wqnL, 512, 512, 0};
    WPrepDesc d1{Wo1,  bcH,  bcL,  512, 512, 1};
    WPrepDesc d2{Wa,   bcH + 512 * 512, bcL + 512 * 512, NHc * NPc, 128, 1};
    WPrepDesc d3{Wo2,  wo2H, wo2L, NHc * NPc * 3, 128, 1};
    WPrepDesc d4{Wout, woH,  woL,  512, 512, 1};
    k_wprep_all<<<dim3(16, 16, 5), dim3(32, 8)>>>(d0, d1, d2, d3, d4);
    // combined bias
    k_bprep<<<5, 128>>>(bq, Wo1, bo1, Wa, ba);
    // B' = Bcat @ WqN  (640x512), split output
    k_sgemm<0,2><<<dim3(4, 5), 256, MG_SMEM>>>(bcH, bcL, wqnH, wqnL, p_bz, nullptr, w1H, w1L, Cc);

    // fused stats + transpose + LN -> split q
    k_lnfuse<<<dim3(250, Bc), 256, LN_SMEM>>>(f_query, ln_g, ln_b);
    // permute KV to fp16 channels-last
    k_perm<<<Bc * NHc * Dim * Dim, 256>>>(f_kv);

    // merged: hid = relu(q@B'[0:512] + bc), attn = q@B'[512:544] + bc
    k_sgemm<1,3><<<dim3(5, 125), 256, MG_SMEM>>>(qH, qL, w1H, w1L, p_bc, p_attn, hH, hL, 544);
    // off = clip(hid @ Wo2 + bo2)
    k_sgemm<2,0><<<dim3(1, 125), 256, MG_SMEM>>>(hH, hL, wo2H, wo2L, bo2, p_off, nullptr, nullptr, NHc * NPc * 3);
    // sampling (softmax fused) -> split samp
    k_sample<<<(MTOT * NHc) * 32 / 256, 256>>>();
    // out = samp @ Wout + bout, transposed store
    k_sgemm<0,1><<<dim3(4, 125), 256, MG_SMEM>>>(sH, sL, woH, woL, bout, out, nullptr, nullptr, Cc);
}

// round 9
// speedup vs baseline: 1.1987x; 1.0726x over previous
#include <cuda_runtime.h>
#include <cuda_bf16.h>
#include <cuda_fp16.h>
#include <cstdint>

#define Bc 2
#define Cc 512
#define NHc 8
#define NPc 4
#define HDc 64
#define Dim 20
#define Nspat 8000          // 20*20*20
#define MTOT (Bc*Nspat)     // 16000
#define LN_EPS 1e-5f

// ---------------- scratch (no allocations allowed) ----------------
// activations: fp16 hi/lo split (A operands)
__device__ __align__(16) __half g_qH  [(size_t)MTOT*Cc];
__device__ __align__(16) __half g_qL  [(size_t)MTOT*Cc];
__device__ __align__(16) __half g_hidH[(size_t)MTOT*Cc];
__device__ __align__(16) __half g_hidL[(size_t)MTOT*Cc];
__device__ __align__(16) __half g_sH  [(size_t)MTOT*Cc];
__device__ __align__(16) __half g_sL  [(size_t)MTOT*Cc];
__device__ __align__(16) float g_off [(size_t)MTOT*NHc*NPc*3];
__device__ __align__(16) float g_attn[(size_t)MTOT*NHc*NPc];
__device__ __align__(16) __half g_feats[(size_t)Bc*NHc*Nspat*HDc];
// weights: fp16 single (B operands), K-major rows
__device__ __align__(256) __half g_W1  [640*512];   // folded [Wo1T;WaT]@Wq
__device__ __align__(256) __half g_Wo2 [128*512];
__device__ __align__(256) __half g_Wout[512*512];
__device__ float g_bc[640];       // merged bias [b1'(512); ba'(32); 0]

// ================= helpers =================
__device__ __forceinline__ uint32_t smem_u32(const void* p) {
    uint32_t a;
    asm("{ .reg .u64 t; cvta.to.shared.u64 t, %1; cvt.u32.u64 %0, t; }" : "=r"(a) : "l"(p));
    return a;
}
__device__ __forceinline__ void ldsm4(uint32_t* r, uint32_t addr) {
    asm volatile("ldmatrix.sync.aligned.m8n8.x4.shared.b16 {%0,%1,%2,%3}, [%4];"
        : "=r"(r[0]), "=r"(r[1]), "=r"(r[2]), "=r"(r[3]) : "r"(addr));
}
__device__ __forceinline__ void mma_f16(float* c, const uint32_t* a, const uint32_t* b) {
    asm volatile(
        "mma.sync.aligned.m16n8k16.row.col.f32.f16.f16.f32 "
        "{%0,%1,%2,%3}, {%4,%5,%6,%7}, {%8,%9}, {%0,%1,%2,%3};"
        : "+f"(c[0]), "+f"(c[1]), "+f"(c[2]), "+f"(c[3])
        : "r"(a[0]), "r"(a[1]), "r"(a[2]), "r"(a[3]), "r"(b[0]), "r"(b[1]));
}
#define CPA16(dst, src) \
    asm volatile("cp.async.cg.shared.global [%0], [%1], 16;" :: "r"(dst), "l"(src) : "memory")

// split fp32 -> fp16 hi/lo half2 pair
__device__ __forceinline__ uint32_t split_h2(float v0, float v1, uint32_t& lo) {
    __half h0 = __float2half_rn(v0), h1 = __float2half_rn(v1);
    __half l0 = __float2half_rn(v0 - __half2float(h0));
    __half l1 = __float2half_rn(v1 - __half2float(h1));
    __half2 hh = __halves2half2(h0, h1), ll = __halves2half2(l0, l1);
    lo = *(uint32_t*)&ll;
    return *(uint32_t*)&hh;
}

// ================= fp16 A-split HMMA GEMM =================
// D = act(A(M,512)@W(512,Nc)+bias). A = AH+AL fp16 (rows,512) K-major; B fp16 single.
// Tile 128x128, BK=32, 2-stage cp.async. 2 MMAs per product: a_h*b + a_l*b.
// stage (80B row stride, 32 fp16/row): Ah@0 Al@10240 B@20480; stage=30720B.
#define MG_STAGE 30720
#define MG_SMEM  (2*MG_STAGE)   // 60KB dynamic

// omode: 0 = fp32 row-major, 1 = fp32 transposed (B,C,Nspat),
//        2 = split fp16 H/L, 3 = merged: col<512 relu+split hid, 512..543 fp32 attn
__device__ __forceinline__ void sgemm_body(
    const __half* __restrict__ AH, const __half* __restrict__ AL,
    const __half* __restrict__ Bs,
    const float* __restrict__ bias,
    float* __restrict__ Cf, __half* __restrict__ CH, __half* __restrict__ CL,
    int Nc, int act, int omode, int m0, int n0, char* sm)
{
    const uint32_t smb = smem_u32(sm);
    const int tid = threadIdx.x;
    const int wid = tid >> 5, lane = tid & 31;
    const int wm = wid >> 1;
    const int wn = wid & 1;

    const int tq = lane >> 3, rr = lane & 7;
    const int a_row = rr + (tq & 1) * 8;
    const int a_col = (tq >> 1) * 8;
    const int b_row = rr + (tq >> 1) * 8;
    const int b_col = (tq & 1) * 8;

    const int r2  = tid >> 1;            // 0..127
    const int kc2 = (tid & 1) * 32;      // byte offset 0/32

    const __half* AHp = AH + (size_t)(m0 + r2) * 512 + (tid & 1) * 16;
    const __half* ALp = AL + (size_t)(m0 + r2) * 512 + (tid & 1) * 16;
    const __half* Bp  = Bs + (size_t)(n0 + r2) * 512 + (tid & 1) * 16;

    auto ldAB = [&](int stage, int kt) {
        uint32_t ro = smb + stage * MG_STAGE + r2 * 80 + kc2;
        const int go = kt * 32;
        CPA16(ro,              AHp + go);
        CPA16(ro + 16,         AHp + go + 8);
        CPA16(ro + 10240,      ALp + go);
        CPA16(ro + 10240 + 16, ALp + go + 8);
        CPA16(ro + 20480,      Bp + go);
        CPA16(ro + 20480 + 16, Bp + go + 8);
        asm volatile("cp.async.commit_group;" ::: "memory");
    };

    float acc[2][8][4];
    #pragma unroll
    for (int mi = 0; mi < 2; ++mi)
        #pragma unroll
        for (int j = 0; j < 8; ++j)
            #pragma unroll
            for (int q = 0; q < 4; ++q) acc[mi][j][q] = 0.f;

    ldAB(0, 0);

    for (int kt = 0; kt < 16; ++kt) {
        int cur = kt & 1, nxt = cur ^ 1;
        if (kt + 1 < 16) {
            ldAB(nxt, kt + 1);
            asm volatile("cp.async.wait_group 1;" ::: "memory");
        } else {
            asm volatile("cp.async.wait_group 0;" ::: "memory");
        }
        __syncthreads();
        uint32_t abase = smb + cur * MG_STAGE;
        uint32_t bbase = abase + 20480;
        #pragma unroll
        for (int ks = 0; ks < 2; ++ks) {
            int kc = ks * 16;
            uint32_t ah[2][4], al[2][4], bf[4][4];
            #pragma unroll
            for (int mi = 0; mi < 2; ++mi) {
                uint32_t ad = abase + (uint32_t)(wm * 32 + mi * 16 + a_row) * 80 + (kc + a_col) * 2;
                ldsm4(ah[mi], ad);
                ldsm4(al[mi], ad + 10240);
            }
            #pragma unroll
            for (int p = 0; p < 4; ++p) {
                uint32_t bd = bbase + (uint32_t)(wn * 64 + p * 16 + b_row) * 80 + (kc + b_col) * 2;
                ldsm4(bf[p], bd);
            }
            #pragma unroll
            for (int mi = 0; mi < 2; ++mi)
                #pragma unroll
                for (int j = 0; j < 8; ++j) {
                    const uint32_t* bp = &bf[j >> 1][(j & 1) * 2];
                    mma_f16(acc[mi][j], ah[mi], bp);
                    mma_f16(acc[mi][j], al[mi], bp);
                }
        }
        __syncthreads();
    }

    #pragma unroll
    for (int mi = 0; mi < 2; ++mi) {
        int row0 = m0 + wm * 32 + mi * 16 + (lane >> 2);
        #pragma unroll
        for (int j = 0; j < 8; ++j) {
            int col0 = n0 + wn * 64 + j * 8 + (lane & 3) * 2;
            if (col0 >= Nc) continue;
            float b0 = bias[col0], b1 = bias[col0 + 1];
            #pragma unroll
            for (int half = 0; half < 2; ++half) {
                int row = row0 + half * 8;
                float v0 = acc[mi][j][half * 2 + 0] + b0;
                float v1 = acc[mi][j][half * 2 + 1] + b1;
                if (omode == 3) {
                    if (col0 < 512) {
                        v0 = fmaxf(v0, 0.f); v1 = fmaxf(v1, 0.f);
                        uint32_t lo, hi = split_h2(v0, v1, lo);
                        *(uint32_t*)(CH + (size_t)row * 512 + col0) = hi;
                        *(uint32_t*)(CL + (size_t)row * 512 + col0) = lo;
                    } else {
                        *(float2*)(Cf + (size_t)row * 32 + (col0 - 512)) = make_float2(v0, v1);
                    }
                    continue;
                }
                if (act == 1) { v0 = fmaxf(v0, 0.f); v1 = fmaxf(v1, 0.f); }
                if (act == 2) {
                    v0 = fminf(fmaxf(v0, -3.f), 3.f);
                    v1 = fminf(fmaxf(v1, -3.f), 3.f);
                }
                if (omode == 0) {
                    *(float2*)(Cf + (size_t)row * Nc + col0) = make_float2(v0, v1);
                } else if (omode == 1) {
                    int b = row / Nspat, n = row - b * Nspat;
                    Cf[((size_t)(b * Cc + col0)) * Nspat + n] = v0;
                    Cf[((size_t)(b * Cc + col0 + 1)) * Nspat + n] = v1;
                } else {
                    uint32_t lo, hi = split_h2(v0, v1, lo);
                    *(uint32_t*)(CH + (size_t)row * Nc + col0) = hi;
                    *(uint32_t*)(CL + (size_t)row * Nc + col0) = lo;
                }
            }
        }
    }
}

template<int ACT, int OMODE>
__global__ void __launch_bounds__(256, 2) k_sgemm(
    const __half* __restrict__ AH, const __half* __restrict__ AL,
    const __half* __restrict__ Bs,
    const float* __restrict__ bias,
    float* __restrict__ Cf, __half* __restrict__ CH, __half* __restrict__ CL,
    int Nc)
{
    extern __shared__ __align__(1024) char sm_dyn[];
    sgemm_body(AH, AL, Bs, bias, Cf, CH, CL, Nc, ACT, OMODE,
               blockIdx.y * 128, blockIdx.x * 128, sm_dyn);
}

// ---------------- exact fp32 weight fold: B'[n][j] = sum_k Wsrc[k][n] * Wq[j][k] ----------------
// n<512: Wsrc=Wo1; 512<=n<544: Wa; else 0. Output fp16 single to g_W1 (640x512).
__global__ void __launch_bounds__(256) k_wfold(const float* __restrict__ Wo1,
                                               const float* __restrict__ Wa,
                                               const float* __restrict__ Wq) {
    __shared__ float T1[32][33];   // [k][n]
    __shared__ float T2[32][33];   // [j][k]
    int j0 = blockIdx.x * 32, n0 = blockIdx.y * 32;
    int tx = threadIdx.x, ty = threadIdx.y;   // (32,8)
    float acc[4] = {0.f, 0.f, 0.f, 0.f};
    for (int k0 = 0; k0 < 512; k0 += 32) {
        #pragma unroll
        for (int i = 0; i < 32; i += 8) {
            int k = k0 + ty + i, n = n0 + tx;
            float v = 0.f;
            if (n < 512)      v = Wo1[(size_t)k * 512 + n];
            else if (n < 544) v = Wa[(size_t)k * 32 + (n - 512)];
            T1[ty + i][tx] = v;
            T2[ty + i][tx] = Wq[(size_t)(j0 + ty + i) * 512 + k0 + tx];
        }
        __syncthreads();
        #pragma unroll 8
        for (int k = 0; k < 32; ++k) {
            float t1 = T1[k][tx];
            #pragma unroll
            for (int r = 0; r < 4; ++r) acc[r] += t1 * T2[ty + 8 * r][k];
        }
        __syncthreads();
    }
    #pragma unroll
    for (int r = 0; r < 4; ++r)
        g_W1[(size_t)(n0 + tx) * 512 + j0 + ty + 8 * r] = __float2half_rn(acc[r]);
}

// ---------------- weight prep: transpose + fp16 convert (Wo2, Wout) ----------------
struct WPrepDesc {
    const float* W;
    __half* H;
    int Ncols;
    int Npad;
};
__global__ void k_wprep_all(WPrepDesc w0, WPrepDesc w1) {
    WPrepDesc d = (blockIdx.z == 0) ? w0 : w1;
    __shared__ float t[32][33];
    int k0 = blockIdx.y * 32, n0 = blockIdx.x * 32;
    if (n0 >= d.Npad) return;
    int tx = threadIdx.x, ty = threadIdx.y;  // (32,8)
    #pragma unroll
    for (int i = 0; i < 32; i += 8) {
        int k = k0 + ty + i, n = n0 + tx;
        t[ty + i][tx] = (n < d.Ncols) ? d.W[(size_t)k * d.Ncols + n] : 0.f;
    }
    __syncthreads();
    #pragma unroll
    for (int i = 0; i < 32; i += 8) {
        int n = n0 + ty + i, k = k0 + tx;
        d.H[(size_t)n * 512 + k] = __float2half_rn(t[tx][ty + i]);
    }
}

// ---------------- bias prep: bc = [bq@Wo1+bo1 (512); bq@Wa+ba (32); 0] ----------------
__global__ void k_bprep(const float* __restrict__ bq,
                        const float* __restrict__ Wo1, const float* __restrict__ bo1,
                        const float* __restrict__ Wa,  const float* __restrict__ ba) {
    int n = blockIdx.x * 128 + threadIdx.x;
    if (n >= 640) return;
    float s = 0.f;
    if (n < 512) {
        s = bo1[n];
        for (int j = 0; j < 512; ++j) s += bq[j] * Wo1[(size_t)j * 512 + n];
    } else if (n < 544) {
        int c = n - 512;
        s = ba[c];
        for (int j = 0; j < 512; ++j) s += bq[j] * Wa[(size_t)j * 32 + c];
    }
    g_bc[n] = s;
}

// ---------------- fused stats + transpose + LN -> split fp16 qH/qL ----------------
__global__ void __launch_bounds__(256) k_lnfuse(const float* __restrict__ fq,
                                                const float* __restrict__ lng,
                                                const float* __restrict__ lnb) {
    extern __shared__ __align__(1024) char sm_dyn[];
    float* sm = (float*)sm_dyn;
    float* smean = sm + 32 * 513;
    float* srstd = smean + 32;
    int b  = blockIdx.y;
    int n0 = blockIdx.x * 32;
    int tid = threadIdx.x;
    int warp = tid >> 5, lane = tid & 31;
    const float* src = fq + (size_t)b * Cc * Nspat + n0 + lane;
    #pragma unroll 8
    for (int it = 0; it < 64; ++it) {
        int c = it * 8 + warp;
        sm[lane * 513 + c] = src[(size_t)c * Nspat];
    }
    __syncthreads();
    #pragma unroll
    for (int i = 0; i < 4; ++i) {
        int tok = warp * 4 + i;
        float s = 0.f, ss = 0.f;
        const float* row = sm + tok * 513;
        #pragma unroll
        for (int j = 0; j < 16; ++j) {
            float v = row[lane + j * 32];
            s += v; ss += v * v;
        }
        #pragma unroll
        for (int o = 16; o > 0; o >>= 1) {
            s  += __shfl_xor_sync(0xffffffffu, s, o);
            ss += __shfl_xor_sync(0xffffffffu, ss, o);
        }
        if (lane == 0) {
            float mu = s * (1.f / Cc);
            float var = ss * (1.f / Cc) - mu * mu;
            smean[tok] = mu;
            srstd[tok] = rsqrtf(var + LN_EPS);
        }
    }
    __syncthreads();
    #pragma unroll
    for (int i = 0; i < 4; ++i) {
        int tok = warp * 4 + i;
        float mu = smean[tok], rs = srstd[tok];
        size_t obase = (size_t)(b * Nspat + n0 + tok) * Cc;
        const float* row = sm + tok * 513;
        #pragma unroll
        for (int k = 0; k < 4; ++k) {
            int c = lane * 4 + k * 128;
            float v0 = (row[c + 0] - mu) * rs * lng[c + 0] + lnb[c + 0];
            float v1 = (row[c + 1] - mu) * rs * lng[c + 1] + lnb[c + 1];
            float v2 = (row[c + 2] - mu) * rs * lng[c + 2] + lnb[c + 2];
            float v3 = (row[c + 3] - mu) * rs * lng[c + 3] + lnb[c + 3];
            uint32_t lo0, hi0 = split_h2(v0, v1, lo0);
            uint32_t lo1, hi1 = split_h2(v2, v3, lo1);
            *(uint2*)(g_qH + obase + c) = make_uint2(hi0, hi1);
            *(uint2*)(g_qL + obase + c) = make_uint2(lo0, lo1);
        }
    }
}

// ---------------- permute f_kv -> (B,NH,D,H,W,HD) as fp16 ----------------
__global__ void k_perm(const float* __restrict__ fkv) {
    __shared__ float s[HDc * 21];
    int blk = blockIdx.x;
    int x = blk % Dim;
    int y = (blk / Dim) % Dim;
    int h = (blk / (Dim * Dim)) % NHc;
    int b = blk / (Dim * Dim * NHc);
    const float* src = fkv + ((size_t)(b * Cc + h * HDc)) * Nspat + (y * Dim + x) * Dim;
    for (int idx = threadIdx.x; idx < HDc * Dim; idx += blockDim.x) {
        int hd = idx / Dim, z = idx - hd * Dim;
        s[hd * 21 + z] = src[(size_t)hd * Nspat + z];
    }
    __syncthreads();
    __half* dst = g_feats + ((size_t)(b * NHc + h) * Nspat) * HDc;
    for (int idx = threadIdx.x; idx < HDc * Dim; idx += blockDim.x) {
        int z = idx / HDc, hd = idx - z * HDc;
        dst[(size_t)((z * Dim + y) * Dim + x) * HDc + hd] = __float2half_rn(s[hd * 21 + z]);
    }
}

// ---------------- trilinear gather + fused softmax + weighted sum ----------------
__global__ void k_sample() {
    int gw   = (blockIdx.x * blockDim.x + threadIdx.x) >> 5;
    int lane = threadIdx.x & 31;
    if (gw >= MTOT * NHc) return;
    int h = gw % NHc;
    int t = gw / NHc;
    int b = t / Nspat;
    int n = t - b * Nspat;
    int y = n / (Dim * Dim);
    int x = (n / Dim) % Dim;
    int z = n % Dim;

    const float* off = g_off + (size_t)gw * NPc * 3;
    float4 lg = ((const float4*)g_attn)[gw];
    float mx = fmaxf(fmaxf(lg.x, lg.y), fmaxf(lg.z, lg.w));
    float e0 = __expf(lg.x - mx), e1 = __expf(lg.y - mx);
    float e2 = __expf(lg.z - mx), e3 = __expf(lg.w - mx);
    float inv = 1.f / (e0 + e1 + e2 + e3);
    float aw[4] = {e0 * inv, e1 * inv, e2 * inv, e3 * inv};

    const __half* feats = g_feats + ((size_t)(b * NHc + h) * Nspat) * HDc;

    float acc0 = 0.f, acc1 = 0.f;
    #pragma unroll
    for (int p = 0; p < NPc; ++p) {
        float ap = aw[p];
        float ix = fminf(fmaxf((float)y + off[p * 3 + 0], 0.f), (float)(Dim - 1));
        float iy = fminf(fmaxf((float)x + off[p * 3 + 1], 0.f), (float)(Dim - 1));
        float iz = fminf(fmaxf((float)z + off[p * 3 + 2], 0.f), (float)(Dim - 1));
        float x0f = floorf(ix), y0f = floorf(iy), z0f = floorf(iz);
        float fx = ix - x0f, fy = iy - y0f, fz = iz - z0f;
        int x0 = (int)x0f, y0 = (int)y0f, z0 = (int)z0f;
        int x1 = min(x0 + 1, Dim - 1);
        int y1 = min(y0 + 1, Dim - 1);
        int z1 = min(z0 + 1, Dim - 1);
        float wx[2] = {1.f - fx, fx};
        float wy[2] = {1.f - fy, fy};
        float wz[2] = {1.f - fz, fz};
        int   xs[2] = {x0, x1}, ys[2] = {y0, y1}, zs[2] = {z0, z1};
        #pragma unroll
        for (int dz = 0; dz < 2; ++dz)
            #pragma unroll
            for (int dy = 0; dy < 2; ++dy)
                #pragma unroll
                for (int dx = 0; dx < 2; ++dx) {
                    float w = ap * wz[dz] * wy[dy] * wx[dx];
                    const __half2* f = (const __half2*)(feats + (size_t)((zs[dz] * Dim + ys[dy]) * Dim + xs[dx]) * HDc);
                    float2 v = __half22float2(f[lane]);
                    acc0 += w * v.x;
                    acc1 += w * v.y;
                }
    }
    size_t oidx = (size_t)t * Cc + h * HDc + lane * 2;
    uint32_t lo, hi = split_h2(acc0, acc1, lo);
    *(uint32_t*)(g_sH + oidx) = hi;
    *(uint32_t*)(g_sL + oidx) = lo;
}

// ---------------- host ----------------
extern "C" void kernel_launch(void* const* d_in, const int* in_sizes, int n_in,
                              void* d_out, int out_size) {
    (void)in_sizes; (void)n_in; (void)out_size;
    const float* f_query = (const float*)d_in[0];
    const float* f_kv    = (const float*)d_in[1];
    const float* ln_g    = (const float*)d_in[2];
    const float* ln_b    = (const float*)d_in[3];
    const float* Wq   = (const float*)d_in[4];
    const float* bq   = (const float*)d_in[5];
    const float* Wo1  = (const float*)d_in[6];
    const float* bo1  = (const float*)d_in[7];
    const float* Wo2  = (const float*)d_in[8];
    const float* bo2  = (const float*)d_in[9];
    const float* Wa   = (const float*)d_in[10];
    const float* ba   = (const float*)d_in[11];
    const float* Wout = (const float*)d_in[12];
    const float* bout = (const float*)d_in[13];
    float* out = (float*)d_out;

    float *p_off, *p_attn, *p_bc;
    cudaGetSymbolAddress((void**)&p_off,  g_off);
    cudaGetSymbolAddress((void**)&p_attn, g_attn);
    cudaGetSymbolAddress((void**)&p_bc,   g_bc);
    __half *qH, *qL, *hH, *hL, *sH, *sL, *w1, *wo2, *wo;
    cudaGetSymbolAddress((void**)&qH, g_qH);   cudaGetSymbolAddress((void**)&qL, g_qL);
    cudaGetSymbolAddress((void**)&hH, g_hidH); cudaGetSymbolAddress((void**)&hL, g_hidL);
    cudaGetSymbolAddress((void**)&sH, g_sH);   cudaGetSymbolAddress((void**)&sL, g_sL);
    cudaGetSymbolAddress((void**)&w1, g_W1);
    cudaGetSymbolAddress((void**)&wo2, g_Wo2);
    cudaGetSymbolAddress((void**)&wo, g_Wout);

    cudaFuncSetAttribute(k_sgemm<1,3>, cudaFuncAttributeMaxDynamicSharedMemorySize, MG_SMEM);
    cudaFuncSetAttribute(k_sgemm<2,0>, cudaFuncAttributeMaxDynamicSharedMemorySize, MG_SMEM);
    cudaFuncSetAttribute(k_sgemm<0,1>, cudaFuncAttributeMaxDynamicSharedMemorySize, MG_SMEM);
    const int LN_SMEM = (32 * 513 + 64) * 4;
    cudaFuncSetAttribute(k_lnfuse, cudaFuncAttributeMaxDynamicSharedMemorySize, LN_SMEM);

    // weight prep: transpose+fp16 Wo2/Wout; exact fp32 fold for W1; combined bias
    WPrepDesc d0{Wout, wo,  512, 512};
    WPrepDesc d1{Wo2,  wo2, NHc * NPc * 3, 128};
    k_wprep_all<<<dim3(16, 16, 2), dim3(32, 8)>>>(d0, d1);
    k_bprep<<<5, 128>>>(bq, Wo1, bo1, Wa, ba);
    k_wfold<<<dim3(16, 20), dim3(32, 8)>>>(Wo1, Wa, Wq);

    // fused stats + transpose + LN -> split fp16 q
    k_lnfuse<<<dim3(250, Bc), 256, LN_SMEM>>>(f_query, ln_g, ln_b);
    // permute KV to fp16 channels-last
    k_perm<<<Bc * NHc * Dim * Dim, 256>>>(f_kv);

    // merged: hid = relu(q@W1[0:512] + bc) -> split fp16, attn = q@W1[512:544] + bc -> fp32
    k_sgemm<1,3><<<dim3(5, 125), 256, MG_SMEM>>>(qH, qL, w1, p_bc, p_attn, hH, hL, 544);
    // off = clip(hid @ Wo2 + bo2)
    k_sgemm<2,0><<<dim3(1, 125), 256, MG_SMEM>>>(hH, hL, wo2, bo2, p_off, nullptr, nullptr, NHc * NPc * 3);
    // sampling (softmax fused) -> split fp16 samp
    k_sample<<<(MTOT * NHc) * 32 / 256, 256>>>();
    // out = samp @ Wout + bout, transposed store
    k_sgemm<0,1><<<dim3(4, 125), 256, MG_SMEM>>>(sH, sL, wo, bout, out, nullptr, nullptr, Cc);
}

// round 10
// speedup vs baseline: 1.3409x; 1.1187x over previous
#include <cuda_runtime.h>
#include <cuda_bf16.h>
#include <cuda_fp16.h>
#include <cstdint>

#define Bc 2
#define Cc 512
#define NHc 8
#define NPc 4
#define HDc 64
#define Dim 20
#define Nspat 8000          // 20*20*20
#define MTOT (Bc*Nspat)     // 16000
#define LN_EPS 1e-5f

// ---------------- scratch (no allocations allowed) ----------------
__device__ __align__(16) __half g_qH  [(size_t)MTOT*Cc];
__device__ __align__(16) __half g_qL  [(size_t)MTOT*Cc];
__device__ __align__(16) __half g_hid [(size_t)MTOT*Cc];     // single fp16
__device__ __align__(16) __half g_s   [(size_t)MTOT*Cc];     // single fp16
__device__ __align__(16) float g_off [(size_t)MTOT*NHc*NPc*3];
__device__ __align__(16) float g_attn[(size_t)MTOT*NHc*NPc];
__device__ __align__(16) __half g_feats[(size_t)Bc*NHc*Nspat*HDc];
// weights fp16 (B operands), K-major rows
__device__ __align__(256) __half g_W1  [640*512];   // folded [Wo1T;WaT]@Wq
__device__ __align__(256) __half g_Wo2 [128*512];
__device__ __align__(256) __half g_Wout[512*512];
__device__ float g_bc[640];       // merged bias

// ================= helpers =================
__device__ __forceinline__ uint32_t smem_u32(const void* p) {
    uint32_t a;
    asm("{ .reg .u64 t; cvta.to.shared.u64 t, %1; cvt.u32.u64 %0, t; }" : "=r"(a) : "l"(p));
    return a;
}
__device__ __forceinline__ void ldsm4(uint32_t* r, uint32_t addr) {
    asm volatile("ldmatrix.sync.aligned.m8n8.x4.shared.b16 {%0,%1,%2,%3}, [%4];"
        : "=r"(r[0]), "=r"(r[1]), "=r"(r[2]), "=r"(r[3]) : "r"(addr));
}
__device__ __forceinline__ void mma_f16(float* c, const uint32_t* a, const uint32_t* b) {
    asm volatile(
        "mma.sync.aligned.m16n8k16.row.col.f32.f16.f16.f32 "
        "{%0,%1,%2,%3}, {%4,%5,%6,%7}, {%8,%9}, {%0,%1,%2,%3};"
        : "+f"(c[0]), "+f"(c[1]), "+f"(c[2]), "+f"(c[3])
        : "r"(a[0]), "r"(a[1]), "r"(a[2]), "r"(a[3]), "r"(b[0]), "r"(b[1]));
}
#define CPA16(dst, src) \
    asm volatile("cp.async.cg.shared.global [%0], [%1], 16;" :: "r"(dst), "l"(src) : "memory")

__device__ __forceinline__ uint32_t split_h2(float v0, float v1, uint32_t& lo) {
    __half h0 = __float2half_rn(v0), h1 = __float2half_rn(v1);
    __half l0 = __float2half_rn(v0 - __half2float(h0));
    __half l1 = __float2half_rn(v1 - __half2float(h1));
    __half2 hh = __halves2half2(h0, h1), ll = __halves2half2(l0, l1);
    lo = *(uint32_t*)&ll;
    return *(uint32_t*)&hh;
}

// ================= fp16 HMMA GEMM =================
// SPLIT: A = AH+AL (2 MMAs/product); else A = AH only (1 MMA).
// Tile 128x128, BK=32, 2-stage cp.async.
// SPLIT stage: Ah@0 Al@10240 B@20480 (30720B). Non-split: Ah@0 B@10240 (20480B).
#define SP_SMEM (2*30720)
#define NS_SMEM (2*20480)

// omode: 0 = fp32 row-major, 1 = fp32 transposed (B,C,Nspat),
//        3 = merged: col<512 relu->fp16 CH, 512..543 fp32 attn Cf
template<bool SPLIT>
__device__ __forceinline__ void sgemm_body(
    const __half* __restrict__ AH, const __half* __restrict__ AL,
    const __half* __restrict__ Bs,
    const float* __restrict__ bias,
    float* __restrict__ Cf, __half* __restrict__ CH,
    int Nc, int act, int omode, int m0, int n0, char* sm)
{
    constexpr int STAGE = SPLIT ? 30720 : 20480;
    constexpr int BOFF  = SPLIT ? 20480 : 10240;
    const uint32_t smb = smem_u32(sm);
    const int tid = threadIdx.x;
    const int wid = tid >> 5, lane = tid & 31;
    const int wm = wid >> 1;
    const int wn = wid & 1;

    const int tq = lane >> 3, rr = lane & 7;
    const int a_row = rr + (tq & 1) * 8;
    const int a_col = (tq >> 1) * 8;
    const int b_row = rr + (tq >> 1) * 8;
    const int b_col = (tq & 1) * 8;

    const int r2  = tid >> 1;            // 0..127
    const int kc2 = (tid & 1) * 32;      // byte offset 0/32

    const __half* AHp = AH + (size_t)(m0 + r2) * 512 + (tid & 1) * 16;
    const __half* ALp = SPLIT ? AL + (size_t)(m0 + r2) * 512 + (tid & 1) * 16 : nullptr;
    const __half* Bp  = Bs + (size_t)(n0 + r2) * 512 + (tid & 1) * 16;

    auto ldAB = [&](int stage, int kt) {
        uint32_t ro = smb + stage * STAGE + r2 * 80 + kc2;
        const int go = kt * 32;
        CPA16(ro,      AHp + go);
        CPA16(ro + 16, AHp + go + 8);
        if (SPLIT) {
            CPA16(ro + 10240,      ALp + go);
            CPA16(ro + 10240 + 16, ALp + go + 8);
        }
        CPA16(ro + BOFF,      Bp + go);
        CPA16(ro + BOFF + 16, Bp + go + 8);
        asm volatile("cp.async.commit_group;" ::: "memory");
    };

    float acc[2][8][4];
    #pragma unroll
    for (int mi = 0; mi < 2; ++mi)
        #pragma unroll
        for (int j = 0; j < 8; ++j)
            #pragma unroll
            for (int q = 0; q < 4; ++q) acc[mi][j][q] = 0.f;

    ldAB(0, 0);

    for (int kt = 0; kt < 16; ++kt) {
        int cur = kt & 1;
        if (kt + 1 < 16) {
            ldAB(cur ^ 1, kt + 1);
            asm volatile("cp.async.wait_group 1;" ::: "memory");
        } else {
            asm volatile("cp.async.wait_group 0;" ::: "memory");
        }
        __syncthreads();
        uint32_t abase = smb + cur * STAGE;
        uint32_t bbase = abase + BOFF;
        #pragma unroll
        for (int ks = 0; ks < 2; ++ks) {
            int kc = ks * 16;
            uint32_t ah[2][4], al[2][4], bf[4][4];
            #pragma unroll
            for (int mi = 0; mi < 2; ++mi) {
                uint32_t ad = abase + (uint32_t)(wm * 32 + mi * 16 + a_row) * 80 + (kc + a_col) * 2;
                ldsm4(ah[mi], ad);
                if (SPLIT) ldsm4(al[mi], ad + 10240);
            }
            #pragma unroll
            for (int p = 0; p < 4; ++p) {
                uint32_t bd = bbase + (uint32_t)(wn * 64 + p * 16 + b_row) * 80 + (kc + b_col) * 2;
                ldsm4(bf[p], bd);
            }
            #pragma unroll
            for (int mi = 0; mi < 2; ++mi)
                #pragma unroll
                for (int j = 0; j < 8; ++j) {
                    const uint32_t* bp = &bf[j >> 1][(j & 1) * 2];
                    mma_f16(acc[mi][j], ah[mi], bp);
                    if (SPLIT) mma_f16(acc[mi][j], al[mi], bp);
                }
        }
        __syncthreads();
    }

    #pragma unroll
    for (int mi = 0; mi < 2; ++mi) {
        int row0 = m0 + wm * 32 + mi * 16 + (lane >> 2);
        #pragma unroll
        for (int j = 0; j < 8; ++j) {
            int col0 = n0 + wn * 64 + j * 8 + (lane & 3) * 2;
            if (col0 >= Nc) continue;
            float b0 = bias[col0], b1 = bias[col0 + 1];
            #pragma unroll
            for (int half = 0; half < 2; ++half) {
                int row = row0 + half * 8;
                float v0 = acc[mi][j][half * 2 + 0] + b0;
                float v1 = acc[mi][j][half * 2 + 1] + b1;
                if (omode == 3) {
                    if (col0 < 512) {
                        v0 = fmaxf(v0, 0.f); v1 = fmaxf(v1, 0.f);
                        *(__half2*)(CH + (size_t)row * 512 + col0) = __floats2half2_rn(v0, v1);
                    } else {
                        *(float2*)(Cf + (size_t)row * 32 + (col0 - 512)) = make_float2(v0, v1);
                    }
                    continue;
                }
                if (act == 1) { v0 = fmaxf(v0, 0.f); v1 = fmaxf(v1, 0.f); }
                if (act == 2) {
                    v0 = fminf(fmaxf(v0, -3.f), 3.f);
                    v1 = fminf(fmaxf(v1, -3.f), 3.f);
                }
                if (omode == 0) {
                    *(float2*)(Cf + (size_t)row * Nc + col0) = make_float2(v0, v1);
                } else {  // omode 1: transposed
                    int b = row / Nspat, n = row - b * Nspat;
                    Cf[((size_t)(b * Cc + col0)) * Nspat + n] = v0;
                    Cf[((size_t)(b * Cc + col0 + 1)) * Nspat + n] = v1;
                }
            }
        }
    }
}

template<int ACT, int OMODE, bool SPLIT>
__global__ void __launch_bounds__(256, 2) k_sgemm(
    const __half* __restrict__ AH, const __half* __restrict__ AL,
    const __half* __restrict__ Bs,
    const float* __restrict__ bias,
    float* __restrict__ Cf, __half* __restrict__ CH,
    int Nc)
{
    extern __shared__ __align__(1024) char sm_dyn[];
    sgemm_body<SPLIT>(AH, AL, Bs, bias, Cf, CH, Nc, ACT, OMODE,
                      blockIdx.y * 128, blockIdx.x * 128, sm_dyn);
}

// ---------------- exact fp32 weight fold: W1[n][j] = sum_k Wsrc[k][n] * Wq[j][k] ----------------
__global__ void __launch_bounds__(256) k_wfold(const float* __restrict__ Wo1,
                                               const float* __restrict__ Wa,
                                               const float* __restrict__ Wq) {
    __shared__ float T1[32][33];
    __shared__ float T2[32][33];
    int j0 = blockIdx.x * 32, n0 = blockIdx.y * 32;
    int tx = threadIdx.x, ty = threadIdx.y;   // (32,8)
    float acc[4] = {0.f, 0.f, 0.f, 0.f};
    for (int k0 = 0; k0 < 512; k0 += 32) {
        #pragma unroll
        for (int i = 0; i < 32; i += 8) {
            int k = k0 + ty + i, n = n0 + tx;
            float v = 0.f;
            if (n < 512)      v = Wo1[(size_t)k * 512 + n];
            else if (n < 544) v = Wa[(size_t)k * 32 + (n - 512)];
            T1[ty + i][tx] = v;
            T2[ty + i][tx] = Wq[(size_t)(j0 + ty + i) * 512 + k0 + tx];
        }
        __syncthreads();
        #pragma unroll 8
        for (int k = 0; k < 32; ++k) {
            float t1 = T1[k][tx];
            #pragma unroll
            for (int r = 0; r < 4; ++r) acc[r] += t1 * T2[ty + 8 * r][k];
        }
        __syncthreads();
    }
    #pragma unroll
    for (int r = 0; r < 4; ++r)
        g_W1[(size_t)(n0 + tx) * 512 + j0 + ty + 8 * r] = __float2half_rn(acc[r]);
}

// ---------------- weight prep: transpose + fp16 (Wo2, Wout) ----------------
struct WPrepDesc {
    const float* W;
    __half* H;
    int Ncols;
    int Npad;
};
__global__ void k_wprep_all(WPrepDesc w0, WPrepDesc w1) {
    WPrepDesc d = (blockIdx.z == 0) ? w0 : w1;
    __shared__ float t[32][33];
    int k0 = blockIdx.y * 32, n0 = blockIdx.x * 32;
    if (n0 >= d.Npad) return;
    int tx = threadIdx.x, ty = threadIdx.y;  // (32,8)
    #pragma unroll
    for (int i = 0; i < 32; i += 8) {
        int k = k0 + ty + i, n = n0 + tx;
        t[ty + i][tx] = (n < d.Ncols) ? d.W[(size_t)k * d.Ncols + n] : 0.f;
    }
    __syncthreads();
    #pragma unroll
    for (int i = 0; i < 32; i += 8) {
        int n = n0 + ty + i, k = k0 + tx;
        d.H[(size_t)n * 512 + k] = __float2half_rn(t[tx][ty + i]);
    }
}

// ---------------- bias prep ----------------
__global__ void k_bprep(const float* __restrict__ bq,
                        const float* __restrict__ Wo1, const float* __restrict__ bo1,
                        const float* __restrict__ Wa,  const float* __restrict__ ba) {
    int n = blockIdx.x * 128 + threadIdx.x;
    if (n >= 640) return;
    float s = 0.f;
    if (n < 512) {
        s = bo1[n];
        for (int j = 0; j < 512; ++j) s += bq[j] * Wo1[(size_t)j * 512 + n];
    } else if (n < 544) {
        int c = n - 512;
        s = ba[c];
        for (int j = 0; j < 512; ++j) s += bq[j] * Wa[(size_t)j * 32 + c];
    }
    g_bc[n] = s;
}

// ---------------- fused stats + transpose + LN -> split fp16 qH/qL ----------------
__global__ void __launch_bounds__(256) k_lnfuse(const float* __restrict__ fq,
                                                const float* __restrict__ lng,
                                                const float* __restrict__ lnb) {
    extern __shared__ __align__(1024) char sm_dyn[];
    float* sm = (float*)sm_dyn;
    float* smean = sm + 32 * 513;
    float* srstd = smean + 32;
    int b  = blockIdx.y;
    int n0 = blockIdx.x * 32;
    int tid = threadIdx.x;
    int warp = tid >> 5, lane = tid & 31;
    const float* src = fq + (size_t)b * Cc * Nspat + n0 + lane;
    #pragma unroll 8
    for (int it = 0; it < 64; ++it) {
        int c = it * 8 + warp;
        sm[lane * 513 + c] = src[(size_t)c * Nspat];
    }
    __syncthreads();
    #pragma unroll
    for (int i = 0; i < 4; ++i) {
        int tok = warp * 4 + i;
        float s = 0.f, ss = 0.f;
        const float* row = sm + tok * 513;
        #pragma unroll
        for (int j = 0; j < 16; ++j) {
            float v = row[lane + j * 32];
            s += v; ss += v * v;
        }
        #pragma unroll
        for (int o = 16; o > 0; o >>= 1) {
            s  += __shfl_xor_sync(0xffffffffu, s, o);
            ss += __shfl_xor_sync(0xffffffffu, ss, o);
        }
        if (lane == 0) {
            float mu = s * (1.f / Cc);
            float var = ss * (1.f / Cc) - mu * mu;
            smean[tok] = mu;
            srstd[tok] = rsqrtf(var + LN_EPS);
        }
    }
    __syncthreads();
    #pragma unroll
    for (int i = 0; i < 4; ++i) {
        int tok = warp * 4 + i;
        float mu = smean[tok], rs = srstd[tok];
        size_t obase = (size_t)(b * Nspat + n0 + tok) * Cc;
        const float* row = sm + tok * 513;
        #pragma unroll
        for (int k = 0; k < 4; ++k) {
            int c = lane * 4 + k * 128;
            float v0 = (row[c + 0] - mu) * rs * lng[c + 0] + lnb[c + 0];
            float v1 = (row[c + 1] - mu) * rs * lng[c + 1] + lnb[c + 1];
            float v2 = (row[c + 2] - mu) * rs * lng[c + 2] + lnb[c + 2];
            float v3 = (row[c + 3] - mu) * rs * lng[c + 3] + lnb[c + 3];
            uint32_t lo0, hi0 = split_h2(v0, v1, lo0);
            uint32_t lo1, hi1 = split_h2(v2, v3, lo1);
            *(uint2*)(g_qH + obase + c) = make_uint2(hi0, hi1);
            *(uint2*)(g_qL + obase + c) = make_uint2(lo0, lo1);
        }
    }
}

// ---------------- permute f_kv -> (B,NH,D,H,W,HD) as fp16 ----------------
__global__ void k_perm(const float* __restrict__ fkv) {
    __shared__ float s[HDc * 21];
    int blk = blockIdx.x;
    int x = blk % Dim;
    int y = (blk / Dim) % Dim;
    int h = (blk / (Dim * Dim)) % NHc;
    int b = blk / (Dim * Dim * NHc);
    const float* src = fkv + ((size_t)(b * Cc + h * HDc)) * Nspat + (y * Dim + x) * Dim;
    for (int idx = threadIdx.x; idx < HDc * Dim; idx += blockDim.x) {
        int hd = idx / Dim, z = idx - hd * Dim;
        s[hd * 21 + z] = src[(size_t)hd * Nspat + z];
    }
    __syncthreads();
    __half* dst = g_feats + ((size_t)(b * NHc + h) * Nspat) * HDc;
    for (int idx = threadIdx.x; idx < HDc * Dim; idx += blockDim.x) {
        int z = idx / HDc, hd = idx - z * HDc;
        dst[(size_t)((z * Dim + y) * Dim + x) * HDc + hd] = __float2half_rn(s[hd * 21 + z]);
    }
}

// ---------------- trilinear gather + fused softmax + weighted sum ----------------
__global__ void k_sample() {
    int gw   = (blockIdx.x * blockDim.x + threadIdx.x) >> 5;
    int lane = threadIdx.x & 31;
    if (gw >= MTOT * NHc) return;
    int h = gw % NHc;
    int t = gw / NHc;
    int b = t / Nspat;
    int n = t - b * Nspat;
    int y = n / (Dim * Dim);
    int x = (n / Dim) % Dim;
    int z = n % Dim;

    const float* off = g_off + (size_t)gw * NPc * 3;
    float4 lg = ((const float4*)g_attn)[gw];
    float mx = fmaxf(fmaxf(lg.x, lg.y), fmaxf(lg.z, lg.w));
    float e0 = __expf(lg.x - mx), e1 = __expf(lg.y - mx);
    float e2 = __expf(lg.z - mx), e3 = __expf(lg.w - mx);
    float inv = 1.f / (e0 + e1 + e2 + e3);
    float aw[4] = {e0 * inv, e1 * inv, e2 * inv, e3 * inv};

    const __half* feats = g_feats + ((size_t)(b * NHc + h) * Nspat) * HDc;

    float acc0 = 0.f, acc1 = 0.f;
    #pragma unroll
    for (int p = 0; p < NPc; ++p) {
        float ap = aw[p];
        float ix = fminf(fmaxf((float)y + off[p * 3 + 0], 0.f), (float)(Dim - 1));
        float iy = fminf(fmaxf((float)x + off[p * 3 + 1], 0.f), (float)(Dim - 1));
        float iz = fminf(fmaxf((float)z + off[p * 3 + 2], 0.f), (float)(Dim - 1));
        float x0f = floorf(ix), y0f = floorf(iy), z0f = floorf(iz);
        float fx = ix - x0f, fy = iy - y0f, fz = iz - z0f;
        int x0 = (int)x0f, y0 = (int)y0f, z0 = (int)z0f;
        int x1 = min(x0 + 1, Dim - 1);
        int y1 = min(y0 + 1, Dim - 1);
        int z1 = min(z0 + 1, Dim - 1);
        float wx[2] = {1.f - fx, fx};
        float wy[2] = {1.f - fy, fy};
        float wz[2] = {1.f - fz, fz};
        int   xs[2] = {x0, x1}, ys[2] = {y0, y1}, zs[2] = {z0, z1};
        #pragma unroll
        for (int dz = 0; dz < 2; ++dz)
            #pragma unroll
            for (int dy = 0; dy < 2; ++dy)
                #pragma unroll
                for (int dx = 0; dx < 2; ++dx) {
                    float w = ap * wz[dz] * wy[dy] * wx[dx];
                    const __half2* f = (const __half2*)(feats + (size_t)((zs[dz] * Dim + ys[dy]) * Dim + xs[dx]) * HDc);
                    float2 v = __half22float2(f[lane]);
                    acc0 += w * v.x;
                    acc1 += w * v.y;
                }
    }
    *(__half2*)(g_s + (size_t)t * Cc + h * HDc + lane * 2) = __floats2half2_rn(acc0, acc1);
}

// ---------------- host ----------------
extern "C" void kernel_launch(void* const* d_in, const int* in_sizes, int n_in,
                              void* d_out, int out_size) {
    (void)in_sizes; (void)n_in; (void)out_size;
    const float* f_query = (const float*)d_in[0];
    const float* f_kv    = (const float*)d_in[1];
    const float* ln_g    = (const float*)d_in[2];
    const float* ln_b    = (const float*)d_in[3];
    const float* Wq   = (const float*)d_in[4];
    const float* bq   = (const float*)d_in[5];
    const float* Wo1  = (const float*)d_in[6];
    const float* bo1  = (const float*)d_in[7];
    const float* Wo2  = (const float*)d_in[8];
    const float* bo2  = (const float*)d_in[9];
    const float* Wa   = (const float*)d_in[10];
    const float* ba   = (const float*)d_in[11];
    const float* Wout = (const float*)d_in[12];
    const float* bout = (const float*)d_in[13];
    float* out = (float*)d_out;

    float *p_off, *p_attn, *p_bc;
    cudaGetSymbolAddress((void**)&p_off,  g_off);
    cudaGetSymbolAddress((void**)&p_attn, g_attn);
    cudaGetSymbolAddress((void**)&p_bc,   g_bc);
    __half *qH, *qL, *hid, *sp, *w1, *wo2, *wo;
    cudaGetSymbolAddress((void**)&qH, g_qH);   cudaGetSymbolAddress((void**)&qL, g_qL);
    cudaGetSymbolAddress((void**)&hid, g_hid);
    cudaGetSymbolAddress((void**)&sp, g_s);
    cudaGetSymbolAddress((void**)&w1, g_W1);
    cudaGetSymbolAddress((void**)&wo2, g_Wo2);
    cudaGetSymbolAddress((void**)&wo, g_Wout);

    cudaFuncSetAttribute((const void*)k_sgemm<1,3,true>,  cudaFuncAttributeMaxDynamicSharedMemorySize, SP_SMEM);
    cudaFuncSetAttribute((const void*)k_sgemm<2,0,false>, cudaFuncAttributeMaxDynamicSharedMemorySize, NS_SMEM);
    cudaFuncSetAttribute((const void*)k_sgemm<0,1,false>, cudaFuncAttributeMaxDynamicSharedMemorySize, NS_SMEM);
    const int LN_SMEM = (32 * 513 + 64) * 4;
    cudaFuncSetAttribute(k_lnfuse, cudaFuncAttributeMaxDynamicSharedMemorySize, LN_SMEM);

    // weight prep
    WPrepDesc d0{Wout, wo,  512, 512};
    WPrepDesc d1{Wo2,  wo2, NHc * NPc * 3, 128};
    k_wprep_all<<<dim3(16, 16, 2), dim3(32, 8)>>>(d0, d1);
    k_bprep<<<5, 128>>>(bq, Wo1, bo1, Wa, ba);
    k_wfold<<<dim3(16, 20), dim3(32, 8)>>>(Wo1, Wa, Wq);

    // fused stats + transpose + LN -> split fp16 q
    k_lnfuse<<<dim3(250, Bc), 256, LN_SMEM>>>(f_query, ln_g, ln_b);
    // permute KV to fp16 channels-last
    k_perm<<<Bc * NHc * Dim * Dim, 256>>>(f_kv);

    // merged: hid = relu(q@W1[0:512] + bc) -> fp16, attn = q@W1[512:544] + bc -> fp32
    k_sgemm<1,3,true><<<dim3(5, 125), 256, SP_SMEM>>>(qH, qL, w1, p_bc, p_attn, hid, 544);
    // off = clip(hid @ Wo2 + bo2)   (single-A)
    k_sgemm<2,0,false><<<dim3(1, 125), 256, NS_SMEM>>>(hid, nullptr, wo2, bo2, p_off, nullptr, NHc * NPc * 3);
    // sampling (softmax fused) -> fp16 samp
    k_sample<<<(MTOT * NHc) * 32 / 256, 256>>>();
    // out = samp @ Wout + bout, transposed store   (single-A)
    k_sgemm<0,1,false><<<dim3(4, 125), 256, NS_SMEM>>>(sp, nullptr, wo, bout, out, nullptr, Cc);
}

// round 11
// speedup vs baseline: 1.4334x; 1.0689x over previous
#include <cuda_runtime.h>
#include <cuda_bf16.h>
#include <cuda_fp16.h>
#include <cstdint>

#define Bc 2
#define Cc 512
#define NHc 8
#define NPc 4
#define HDc 64
#define Dim 20
#define Nspat 8000          // 20*20*20
#define MTOT (Bc*Nspat)     // 16000
#define LN_EPS 1e-5f

// ---------------- scratch (no allocations allowed) ----------------
__device__ __align__(16) __half g_q   [(size_t)MTOT*Cc];     // single fp16
__device__ __align__(16) __half g_hid [(size_t)MTOT*Cc];     // single fp16
__device__ __align__(16) __half g_s   [(size_t)MTOT*Cc];     // single fp16
__device__ __align__(16) float g_off [(size_t)MTOT*NHc*NPc*3];
__device__ __align__(16) float g_attn[(size_t)MTOT*NHc*NPc];
__device__ __align__(16) __half g_feats[(size_t)Bc*NHc*Nspat*HDc];
// weights fp16 (B operands), K-major rows
__device__ __align__(256) __half g_W1  [640*512];   // folded [Wo1T;WaT]@Wq
__device__ __align__(256) __half g_Wo2 [128*512];
__device__ __align__(256) __half g_Wout[512*512];
__device__ float g_bc[640];       // merged bias

// ================= helpers =================
__device__ __forceinline__ uint32_t smem_u32(const void* p) {
    uint32_t a;
    asm("{ .reg .u64 t; cvta.to.shared.u64 t, %1; cvt.u32.u64 %0, t; }" : "=r"(a) : "l"(p));
    return a;
}
__device__ __forceinline__ void ldsm4(uint32_t* r, uint32_t addr) {
    asm volatile("ldmatrix.sync.aligned.m8n8.x4.shared.b16 {%0,%1,%2,%3}, [%4];"
        : "=r"(r[0]), "=r"(r[1]), "=r"(r[2]), "=r"(r[3]) : "r"(addr));
}
__device__ __forceinline__ void mma_f16(float* c, const uint32_t* a, const uint32_t* b) {
    asm volatile(
        "mma.sync.aligned.m16n8k16.row.col.f32.f16.f16.f32 "
        "{%0,%1,%2,%3}, {%4,%5,%6,%7}, {%8,%9}, {%0,%1,%2,%3};"
        : "+f"(c[0]), "+f"(c[1]), "+f"(c[2]), "+f"(c[3])
        : "r"(a[0]), "r"(a[1]), "r"(a[2]), "r"(a[3]), "r"(b[0]), "r"(b[1]));
}
#define CPA16(dst, src) \
    asm volatile("cp.async.cg.shared.global [%0], [%1], 16;" :: "r"(dst), "l"(src) : "memory")

// ================= fp16 HMMA GEMM (single-A, 1 MMA/product) =================
// Tile 128x128, BK=32, 2-stage cp.async. stage: A@0 B@10240 (20480B).
#define NS_SMEM (2*20480)      // 40KB
#define TR_SMEM (128*129*4)    // 66048B for staged transposed epilogue

// omode: 0 = fp32 row-major, 1 = fp32 transposed (B,C,Nspat) via smem staging,
//        3 = merged: col<512 relu->fp16 CH, 512..543 fp32 attn Cf
__device__ __forceinline__ void sgemm_body(
    const __half* __restrict__ AH,
    const __half* __restrict__ Bs,
    const float* __restrict__ bias,
    float* __restrict__ Cf, __half* __restrict__ CH,
    int Nc, int act, int omode, int m0, int n0, char* sm)
{
    constexpr int STAGE = 20480;
    constexpr int BOFF  = 10240;
    const uint32_t smb = smem_u32(sm);
    const int tid = threadIdx.x;
    const int wid = tid >> 5, lane = tid & 31;
    const int wm = wid >> 1;
    const int wn = wid & 1;

    const int tq = lane >> 3, rr = lane & 7;
    const int a_row = rr + (tq & 1) * 8;
    const int a_col = (tq >> 1) * 8;
    const int b_row = rr + (tq >> 1) * 8;
    const int b_col = (tq & 1) * 8;

    const int r2  = tid >> 1;            // 0..127
    const int kc2 = (tid & 1) * 32;      // byte offset 0/32

    const __half* AHp = AH + (size_t)(m0 + r2) * 512 + (tid & 1) * 16;
    const __half* Bp  = Bs + (size_t)(n0 + r2) * 512 + (tid & 1) * 16;

    auto ldAB = [&](int stage, int kt) {
        uint32_t ro = smb + stage * STAGE + r2 * 80 + kc2;
        const int go = kt * 32;
        CPA16(ro,             AHp + go);
        CPA16(ro + 16,        AHp + go + 8);
        CPA16(ro + BOFF,      Bp + go);
        CPA16(ro + BOFF + 16, Bp + go + 8);
        asm volatile("cp.async.commit_group;" ::: "memory");
    };

    float acc[2][8][4];
    #pragma unroll
    for (int mi = 0; mi < 2; ++mi)
        #pragma unroll
        for (int j = 0; j < 8; ++j)
            #pragma unroll
            for (int q = 0; q < 4; ++q) acc[mi][j][q] = 0.f;

    ldAB(0, 0);

    for (int kt = 0; kt < 16; ++kt) {
        int cur = kt & 1;
        if (kt + 1 < 16) {
            ldAB(cur ^ 1, kt + 1);
            asm volatile("cp.async.wait_group 1;" ::: "memory");
        } else {
            asm volatile("cp.async.wait_group 0;" ::: "memory");
        }
        __syncthreads();
        uint32_t abase = smb + cur * STAGE;
        uint32_t bbase = abase + BOFF;
        #pragma unroll
        for (int ks = 0; ks < 2; ++ks) {
            int kc = ks * 16;
            uint32_t ah[2][4], bf[4][4];
            #pragma unroll
            for (int mi = 0; mi < 2; ++mi) {
                uint32_t ad = abase + (uint32_t)(wm * 32 + mi * 16 + a_row) * 80 + (kc + a_col) * 2;
                ldsm4(ah[mi], ad);
            }
            #pragma unroll
            for (int p = 0; p < 4; ++p) {
                uint32_t bd = bbase + (uint32_t)(wn * 64 + p * 16 + b_row) * 80 + (kc + b_col) * 2;
                ldsm4(bf[p], bd);
            }
            #pragma unroll
            for (int mi = 0; mi < 2; ++mi)
                #pragma unroll
                for (int j = 0; j < 8; ++j)
                    mma_f16(acc[mi][j], ah[mi], &bf[j >> 1][(j & 1) * 2]);
        }
        __syncthreads();
    }

    if (omode == 1) {
        // stage tile (bias applied), then coalesced transposed stores
        float* smf = (float*)sm;   // [128][129]
        #pragma unroll
        for (int mi = 0; mi < 2; ++mi) {
            #pragma unroll
            for (int j = 0; j < 8; ++j) {
                int c0 = wn * 64 + j * 8 + (lane & 3) * 2;
                float b0 = bias[n0 + c0], b1 = bias[n0 + c0 + 1];
                #pragma unroll
                for (int half = 0; half < 2; ++half) {
                    int r = wm * 32 + mi * 16 + (lane >> 2) + half * 8;
                    smf[r * 129 + c0]     = acc[mi][j][half * 2 + 0] + b0;
                    smf[r * 129 + c0 + 1] = acc[mi][j][half * 2 + 1] + b1;
                }
            }
        }
        __syncthreads();
        #pragma unroll 4
        for (int i = 0; i < 64; ++i) {
            int idx = i * 256 + tid;        // 0..16383
            int cl = idx >> 7, rl = idx & 127;
            int row = m0 + rl;
            int b = row / Nspat, n = row - b * Nspat;
            Cf[((size_t)(b * Cc + n0 + cl)) * Nspat + n] = smf[rl * 129 + cl];
        }
        return;
    }

    #pragma unroll
    for (int mi = 0; mi < 2; ++mi) {
        int row0 = m0 + wm * 32 + mi * 16 + (lane >> 2);
        #pragma unroll
        for (int j = 0; j < 8; ++j) {
            int col0 = n0 + wn * 64 + j * 8 + (lane & 3) * 2;
            if (col0 >= Nc) continue;
            float b0 = bias[col0], b1 = bias[col0 + 1];
            #pragma unroll
            for (int half = 0; half < 2; ++half) {
                int row = row0 + half * 8;
                float v0 = acc[mi][j][half * 2 + 0] + b0;
                float v1 = acc[mi][j][half * 2 + 1] + b1;
                if (omode == 3) {
                    if (col0 < 512) {
                        v0 = fmaxf(v0, 0.f); v1 = fmaxf(v1, 0.f);
                        *(__half2*)(CH + (size_t)row * 512 + col0) = __floats2half2_rn(v0, v1);
                    } else {
                        *(float2*)(Cf + (size_t)row * 32 + (col0 - 512)) = make_float2(v0, v1);
                    }
                    continue;
                }
                if (act == 2) {
                    v0 = fminf(fmaxf(v0, -3.f), 3.f);
                    v1 = fminf(fmaxf(v1, -3.f), 3.f);
                }
                *(float2*)(Cf + (size_t)row * Nc + col0) = make_float2(v0, v1);
            }
        }
    }
}

template<int ACT, int OMODE>
__global__ void __launch_bounds__(256, 2) k_sgemm(
    const __half* __restrict__ AH,
    const __half* __restrict__ Bs,
    const float* __restrict__ bias,
    float* __restrict__ Cf, __half* __restrict__ CH,
    int Nc)
{
    extern __shared__ __align__(1024) char sm_dyn[];
    sgemm_body(AH, Bs, bias, Cf, CH, Nc, ACT, OMODE,
               blockIdx.y * 128, blockIdx.x * 128, sm_dyn);
}

// ---------------- exact fp32 weight fold: W1[n][j] = sum_k Wsrc[k][n] * Wq[j][k] ----------------
__global__ void __launch_bounds__(256) k_wfold(const float* __restrict__ Wo1,
                                               const float* __restrict__ Wa,
                                               const float* __restrict__ Wq) {
    __shared__ float T1[32][33];
    __shared__ float T2[32][33];
    int j0 = blockIdx.x * 32, n0 = blockIdx.y * 32;
    int tx = threadIdx.x, ty = threadIdx.y;   // (32,8)
    float acc[4] = {0.f, 0.f, 0.f, 0.f};
    for (int k0 = 0; k0 < 512; k0 += 32) {
        #pragma unroll
        for (int i = 0; i < 32; i += 8) {
            int k = k0 + ty + i, n = n0 + tx;
            float v = 0.f;
            if (n < 512)      v = Wo1[(size_t)k * 512 + n];
            else if (n < 544) v = Wa[(size_t)k * 32 + (n - 512)];
            T1[ty + i][tx] = v;
            T2[ty + i][tx] = Wq[(size_t)(j0 + ty + i) * 512 + k0 + tx];
        }
        __syncthreads();
        #pragma unroll 8
        for (int k = 0; k < 32; ++k) {
            float t1 = T1[k][tx];
            #pragma unroll
            for (int r = 0; r < 4; ++r) acc[r] += t1 * T2[ty + 8 * r][k];
        }
        __syncthreads();
    }
    #pragma unroll
    for (int r = 0; r < 4; ++r)
        g_W1[(size_t)(n0 + tx) * 512 + j0 + ty + 8 * r] = __float2half_rn(acc[r]);
}

// ---------------- weight prep: transpose + fp16 (Wo2, Wout) ----------------
struct WPrepDesc {
    const float* W;
    __half* H;
    int Ncols;
    int Npad;
};
__global__ void k_wprep_all(WPrepDesc w0, WPrepDesc w1) {
    WPrepDesc d = (blockIdx.z == 0) ? w0 : w1;
    __shared__ float t[32][33];
    int k0 = blockIdx.y * 32, n0 = blockIdx.x * 32;
    if (n0 >= d.Npad) return;
    int tx = threadIdx.x, ty = threadIdx.y;  // (32,8)
    #pragma unroll
    for (int i = 0; i < 32; i += 8) {
        int k = k0 + ty + i, n = n0 + tx;
        t[ty + i][tx] = (n < d.Ncols) ? d.W[(size_t)k * d.Ncols + n] : 0.f;
    }
    __syncthreads();
    #pragma unroll
    for (int i = 0; i < 32; i += 8) {
        int n = n0 + ty + i, k = k0 + tx;
        d.H[(size_t)n * 512 + k] = __float2half_rn(t[tx][ty + i]);
    }
}

// ---------------- bias prep ----------------
__global__ void k_bprep(const float* __restrict__ bq,
                        const float* __restrict__ Wo1, const float* __restrict__ bo1,
                        const float* __restrict__ Wa,  const float* __restrict__ ba) {
    int n = blockIdx.x * 128 + threadIdx.x;
    if (n >= 640) return;
    float s = 0.f;
    if (n < 512) {
        s = bo1[n];
        for (int j = 0; j < 512; ++j) s += bq[j] * Wo1[(size_t)j * 512 + n];
    } else if (n < 544) {
        int c = n - 512;
        s = ba[c];
        for (int j = 0; j < 512; ++j) s += bq[j] * Wa[(size_t)j * 32 + c];
    }
    g_bc[n] = s;
}

// ---------------- fused stats + transpose + LN -> fp16 q ----------------
__global__ void __launch_bounds__(256) k_lnfuse(const float* __restrict__ fq,
                                                const float* __restrict__ lng,
                                                const float* __restrict__ lnb) {
    extern __shared__ __align__(1024) char sm_dyn[];
    float* sm = (float*)sm_dyn;
    float* smean = sm + 32 * 513;
    float* srstd = smean + 32;
    int b  = blockIdx.y;
    int n0 = blockIdx.x * 32;
    int tid = threadIdx.x;
    int warp = tid >> 5, lane = tid & 31;
    const float* src = fq + (size_t)b * Cc * Nspat + n0 + lane;
    #pragma unroll 8
    for (int it = 0; it < 64; ++it) {
        int c = it * 8 + warp;
        sm[lane * 513 + c] = src[(size_t)c * Nspat];
    }
    __syncthreads();
    #pragma unroll
    for (int i = 0; i < 4; ++i) {
        int tok = warp * 4 + i;
        float s = 0.f, ss = 0.f;
        const float* row = sm + tok * 513;
        #pragma unroll
        for (int j = 0; j < 16; ++j) {
            float v = row[lane + j * 32];
            s += v; ss += v * v;
        }
        #pragma unroll
        for (int o = 16; o > 0; o >>= 1) {
            s  += __shfl_xor_sync(0xffffffffu, s, o);
            ss += __shfl_xor_sync(0xffffffffu, ss, o);
        }
        if (lane == 0) {
            float mu = s * (1.f / Cc);
            float var = ss * (1.f / Cc) - mu * mu;
            smean[tok] = mu;
            srstd[tok] = rsqrtf(var + LN_EPS);
        }
    }
    __syncthreads();
    #pragma unroll
    for (int i = 0; i < 4; ++i) {
        int tok = warp * 4 + i;
        float mu = smean[tok], rs = srstd[tok];
        size_t obase = (size_t)(b * Nspat + n0 + tok) * Cc;
        const float* row = sm + tok * 513;
        #pragma unroll
        for (int k = 0; k < 4; ++k) {
            int c = lane * 4 + k * 128;
            float v0 = (row[c + 0] - mu) * rs * lng[c + 0] + lnb[c + 0];
            float v1 = (row[c + 1] - mu) * rs * lng[c + 1] + lnb[c + 1];
            float v2 = (row[c + 2] - mu) * rs * lng[c + 2] + lnb[c + 2];
            float v3 = (row[c + 3] - mu) * rs * lng[c + 3] + lnb[c + 3];
            __half2 h01 = __floats2half2_rn(v0, v1);
            __half2 h23 = __floats2half2_rn(v2, v3);
            *(uint2*)(g_q + obase + c) = make_uint2(*(uint32_t*)&h01, *(uint32_t*)&h23);
        }
    }
}

// ---------------- permute f_kv -> (B,NH,D,H,W,HD) as fp16 ----------------
__global__ void k_perm(const float* __restrict__ fkv) {
    __shared__ float s[HDc * 21];
    int blk = blockIdx.x;
    int x = blk % Dim;
    int y = (blk / Dim) % Dim;
    int h = (blk / (Dim * Dim)) % NHc;
    int b = blk / (Dim * Dim * NHc);
    const float* src = fkv + ((size_t)(b * Cc + h * HDc)) * Nspat + (y * Dim + x) * Dim;
    for (int idx = threadIdx.x; idx < HDc * Dim; idx += blockDim.x) {
        int hd = idx / Dim, z = idx - hd * Dim;
        s[hd * 21 + z] = src[(size_t)hd * Nspat + z];
    }
    __syncthreads();
    __half* dst = g_feats + ((size_t)(b * NHc + h) * Nspat) * HDc;
    for (int idx = threadIdx.x; idx < HDc * Dim; idx += blockDim.x) {
        int z = idx / HDc, hd = idx - z * HDc;
        dst[(size_t)((z * Dim + y) * Dim + x) * HDc + hd] = __float2half_rn(s[hd * 21 + z]);
    }
}

// ---------------- trilinear gather + fused softmax + weighted sum ----------------
__global__ void k_sample() {
    int gw   = (blockIdx.x * blockDim.x + threadIdx.x) >> 5;
    int lane = threadIdx.x & 31;
    if (gw >= MTOT * NHc) return;
    int h = gw % NHc;
    int t = gw / NHc;
    int b = t / Nspat;
    int n = t - b * Nspat;
    int y = n / (Dim * Dim);
    int x = (n / Dim) % Dim;
    int z = n % Dim;

    const float* off = g_off + (size_t)gw * NPc * 3;
    float4 lg = ((const float4*)g_attn)[gw];
    float mx = fmaxf(fmaxf(lg.x, lg.y), fmaxf(lg.z, lg.w));
    float e0 = __expf(lg.x - mx), e1 = __expf(lg.y - mx);
    float e2 = __expf(lg.z - mx), e3 = __expf(lg.w - mx);
    float inv = 1.f / (e0 + e1 + e2 + e3);
    float aw[4] = {e0 * inv, e1 * inv, e2 * inv, e3 * inv};

    const __half* feats = g_feats + ((size_t)(b * NHc + h) * Nspat) * HDc;

    float acc0 = 0.f, acc1 = 0.f;
    #pragma unroll
    for (int p = 0; p < NPc; ++p) {
        float ap = aw[p];
        float ix = fminf(fmaxf((float)y + off[p * 3 + 0], 0.f), (float)(Dim - 1));
        float iy = fminf(fmaxf((float)x + off[p * 3 + 1], 0.f), (float)(Dim - 1));
        float iz = fminf(fmaxf((float)z + off[p * 3 + 2], 0.f), (float)(Dim - 1));
        float x0f = floorf(ix), y0f = floorf(iy), z0f = floorf(iz);
        float fx = ix - x0f, fy = iy - y0f, fz = iz - z0f;
        int x0 = (int)x0f, y0 = (int)y0f, z0 = (int)z0f;
        int x1 = min(x0 + 1, Dim - 1);
        int y1 = min(y0 + 1, Dim - 1);
        int z1 = min(z0 + 1, Dim - 1);
        float wx[2] = {1.f - fx, fx};
        float wy[2] = {1.f - fy, fy};
        float wz[2] = {1.f - fz, fz};
        int   xs[2] = {x0, x1}, ys[2] = {y0, y1}, zs[2] = {z0, z1};
        #pragma unroll
        for (int dz = 0; dz < 2; ++dz)
            #pragma unroll
            for (int dy = 0; dy < 2; ++dy)
                #pragma unroll
                for (int dx = 0; dx < 2; ++dx) {
                    float w = ap * wz[dz] * wy[dy] * wx[dx];
                    const __half2* f = (const __half2*)(feats + (size_t)((zs[dz] * Dim + ys[dy]) * Dim + xs[dx]) * HDc);
                    float2 v = __half22float2(f[lane]);
                    acc0 += w * v.x;
                    acc1 += w * v.y;
                }
    }
    *(__half2*)(g_s + (size_t)t * Cc + h * HDc + lane * 2) = __floats2half2_rn(acc0, acc1);
}

// ---------------- host ----------------
extern "C" void kernel_launch(void* const* d_in, const int* in_sizes, int n_in,
                              void* d_out, int out_size) {
    (void)in_sizes; (void)n_in; (void)out_size;
    const float* f_query = (const float*)d_in[0];
    const float* f_kv    = (const float*)d_in[1];
    const float* ln_g    = (const float*)d_in[2];
    const float* ln_b    = (const float*)d_in[3];
    const float* Wq   = (const float*)d_in[4];
    const float* bq   = (const float*)d_in[5];
    const float* Wo1  = (const float*)d_in[6];
    const float* bo1  = (const float*)d_in[7];
    const float* Wo2  = (const float*)d_in[8];
    const float* bo2  = (const float*)d_in[9];
    const float* Wa   = (const float*)d_in[10];
    const float* ba   = (const float*)d_in[11];
    const float* Wout = (const float*)d_in[12];
    const float* bout = (const float*)d_in[13];
    float* out = (float*)d_out;

    float *p_off, *p_attn, *p_bc;
    cudaGetSymbolAddress((void**)&p_off,  g_off);
    cudaGetSymbolAddress((void**)&p_attn, g_attn);
    cudaGetSymbolAddress((void**)&p_bc,   g_bc);
    __half *q, *hid, *sp, *w1, *wo2, *wo;
    cudaGetSymbolAddress((void**)&q, g_q);
    cudaGetSymbolAddress((void**)&hid, g_hid);
    cudaGetSymbolAddress((void**)&sp, g_s);
    cudaGetSymbolAddress((void**)&w1, g_W1);
    cudaGetSymbolAddress((void**)&wo2, g_Wo2);
    cudaGetSymbolAddress((void**)&wo, g_Wout);

    cudaFuncSetAttribute((const void*)k_sgemm<1,3>, cudaFuncAttributeMaxDynamicSharedMemorySize, NS_SMEM);
    cudaFuncSetAttribute((const void*)k_sgemm<2,0>, cudaFuncAttributeMaxDynamicSharedMemorySize, NS_SMEM);
    cudaFuncSetAttribute((const void*)k_sgemm<0,1>, cudaFuncAttributeMaxDynamicSharedMemorySize, TR_SMEM);
    const int LN_SMEM = (32 * 513 + 64) * 4;
    cudaFuncSetAttribute(k_lnfuse, cudaFuncAttributeMaxDynamicSharedMemorySize, LN_SMEM);

    // weight prep
    WPrepDesc d0{Wout, wo,  512, 512};
    WPrepDesc d1{Wo2,  wo2, NHc * NPc * 3, 128};
    k_wprep_all<<<dim3(16, 16, 2), dim3(32, 8)>>>(d0, d1);
    k_bprep<<<5, 128>>>(bq, Wo1, bo1, Wa, ba);
    k_wfold<<<dim3(16, 20), dim3(32, 8)>>>(Wo1, Wa, Wq);

    // fused stats + transpose + LN -> fp16 q
    k_lnfuse<<<dim3(250, Bc), 256, LN_SMEM>>>(f_query, ln_g, ln_b);
    // permute KV to fp16 channels-last
    k_perm<<<Bc * NHc * Dim * Dim, 256>>>(f_kv);

    // merged: hid = relu(q@W1[0:512] + bc) -> fp16, attn = q@W1[512:544] + bc -> fp32
    k_sgemm<1,3><<<dim3(5, 125), 256, NS_SMEM>>>(q, w1, p_bc, p_attn, hid, 544);
    // off = clip(hid @ Wo2 + bo2)
    k_sgemm<2,0><<<dim3(1, 125), 256, NS_SMEM>>>(hid, wo2, bo2, p_off, nullptr, NHc * NPc * 3);
    // sampling (softmax fused) -> fp16 samp
    k_sample<<<(MTOT * NHc) * 32 / 256, 256>>>();
    // out = samp @ Wout + bout, staged coalesced transposed store
    k_sgemm<0,1><<<dim3(4, 125), 256, TR_SMEM>>>(sp, wo, bout, out, nullptr, Cc);
}

// round 12
// speedup vs baseline: 1.5758x; 1.0994x over previous
#include <cuda_runtime.h>
#include <cuda_bf16.h>
#include <cuda_fp16.h>
#include <cstdint>

#define Bc 2
#define Cc 512
#define NHc 8
#define NPc 4
#define HDc 64
#define Dim 20
#define Nspat 8000          // 20*20*20
#define MTOT (Bc*Nspat)     // 16000
#define LN_EPS 1e-5f

// ---------------- scratch ----------------
__device__ __align__(16) __half g_q   [(size_t)MTOT*Cc];
__device__ __align__(16) __half g_hid [(size_t)MTOT*Cc];
__device__ __align__(16) __half g_s   [(size_t)MTOT*Cc];
__device__ __align__(16) float g_off [(size_t)MTOT*NHc*NPc*3];
__device__ __align__(16) float g_attn[(size_t)MTOT*NHc*NPc];
__device__ __align__(16) __half g_feats[(size_t)Bc*NHc*Nspat*HDc];
__device__ __align__(256) __half g_W1  [640*512];   // folded [Wo1T;WaT]@Wq
__device__ __align__(256) __half g_Wo2 [128*512];
__device__ __align__(256) __half g_Wout[512*512];
__device__ float g_bc[640];

// ================= helpers =================
__device__ __forceinline__ uint32_t smem_u32(const void* p) {
    uint32_t a;
    asm("{ .reg .u64 t; cvta.to.shared.u64 t, %1; cvt.u32.u64 %0, t; }" : "=r"(a) : "l"(p));
    return a;
}
__device__ __forceinline__ void ldsm4(uint32_t* r, uint32_t addr) {
    asm volatile("ldmatrix.sync.aligned.m8n8.x4.shared.b16 {%0,%1,%2,%3}, [%4];"
        : "=r"(r[0]), "=r"(r[1]), "=r"(r[2]), "=r"(r[3]) : "r"(addr));
}
__device__ __forceinline__ void mma_f16(float* c, const uint32_t* a, const uint32_t* b) {
    asm volatile(
        "mma.sync.aligned.m16n8k16.row.col.f32.f16.f16.f32 "
        "{%0,%1,%2,%3}, {%4,%5,%6,%7}, {%8,%9}, {%0,%1,%2,%3};"
        : "+f"(c[0]), "+f"(c[1]), "+f"(c[2]), "+f"(c[3])
        : "r"(a[0]), "r"(a[1]), "r"(a[2]), "r"(a[3]), "r"(b[0]), "r"(b[1]));
}
#define CPA16(dst, src) \
    asm volatile("cp.async.cg.shared.global [%0], [%1], 16;" :: "r"(dst), "l"(src) : "memory")

// ================= fp16 HMMA GEMM (single-A, 1 MMA/product) =================
// Tile 128x128, BK=32, 2-stage cp.async. stage: A@0 B@10240 (20480B).
#define NS_SMEM (2*20480)      // 40KB
#define TR_SMEM (128*129*4)    // 66048B for staged transposed epilogue

// omode: 0 = fp32 row-major (+act: 0 none, 2 clip), 1 = fp32 transposed staged,
//        2 = relu -> fp16
__device__ __forceinline__ void sgemm_body(
    const __half* __restrict__ AH,
    const __half* __restrict__ Bs,
    const float* __restrict__ bias,
    float* __restrict__ Cf, __half* __restrict__ CH,
    int Nc, int act, int omode, int m0, int n0, char* sm)
{
    constexpr int STAGE = 20480;
    constexpr int BOFF  = 10240;
    const uint32_t smb = smem_u32(sm);
    const int tid = threadIdx.x;
    const int wid = tid >> 5, lane = tid & 31;
    const int wm = wid >> 1;
    const int wn = wid & 1;

    const int tq = lane >> 3, rr = lane & 7;
    const int a_row = rr + (tq & 1) * 8;
    const int a_col = (tq >> 1) * 8;
    const int b_row = rr + (tq >> 1) * 8;
    const int b_col = (tq & 1) * 8;

    const int r2  = tid >> 1;
    const int kc2 = (tid & 1) * 32;

    const __half* AHp = AH + (size_t)(m0 + r2) * 512 + (tid & 1) * 16;
    const __half* Bp  = Bs + (size_t)(n0 + r2) * 512 + (tid & 1) * 16;

    auto ldAB = [&](int stage, int kt) {
        uint32_t ro = smb + stage * STAGE + r2 * 80 + kc2;
        const int go = kt * 32;
        CPA16(ro,             AHp + go);
        CPA16(ro + 16,        AHp + go + 8);
        CPA16(ro + BOFF,      Bp + go);
        CPA16(ro + BOFF + 16, Bp + go + 8);
        asm volatile("cp.async.commit_group;" ::: "memory");
    };

    float acc[2][8][4];
    #pragma unroll
    for (int mi = 0; mi < 2; ++mi)
        #pragma unroll
        for (int j = 0; j < 8; ++j)
            #pragma unroll
            for (int q = 0; q < 4; ++q) acc[mi][j][q] = 0.f;

    ldAB(0, 0);

    for (int kt = 0; kt < 16; ++kt) {
        int cur = kt & 1;
        if (kt + 1 < 16) {
            ldAB(cur ^ 1, kt + 1);
            asm volatile("cp.async.wait_group 1;" ::: "memory");
        } else {
            asm volatile("cp.async.wait_group 0;" ::: "memory");
        }
        __syncthreads();
        uint32_t abase = smb + cur * STAGE;
        uint32_t bbase = abase + BOFF;
        #pragma unroll
        for (int ks = 0; ks < 2; ++ks) {
            int kc = ks * 16;
            uint32_t ah[2][4], bf[4][4];
            #pragma unroll
            for (int mi = 0; mi < 2; ++mi) {
                uint32_t ad = abase + (uint32_t)(wm * 32 + mi * 16 + a_row) * 80 + (kc + a_col) * 2;
                ldsm4(ah[mi], ad);
            }
            #pragma unroll
            for (int p = 0; p < 4; ++p) {
                uint32_t bd = bbase + (uint32_t)(wn * 64 + p * 16 + b_row) * 80 + (kc + b_col) * 2;
                ldsm4(bf[p], bd);
            }
            #pragma unroll
            for (int mi = 0; mi < 2; ++mi)
                #pragma unroll
                for (int j = 0; j < 8; ++j)
                    mma_f16(acc[mi][j], ah[mi], &bf[j >> 1][(j & 1) * 2]);
        }
        __syncthreads();
    }

    if (omode == 1) {
        float* smf = (float*)sm;   // [128][129]
        #pragma unroll
        for (int mi = 0; mi < 2; ++mi) {
            #pragma unroll
            for (int j = 0; j < 8; ++j) {
                int c0 = wn * 64 + j * 8 + (lane & 3) * 2;
                float b0 = bias[n0 + c0], b1 = bias[n0 + c0 + 1];
                #pragma unroll
                for (int half = 0; half < 2; ++half) {
                    int r = wm * 32 + mi * 16 + (lane >> 2) + half * 8;
                    smf[r * 129 + c0]     = acc[mi][j][half * 2 + 0] + b0;
                    smf[r * 129 + c0 + 1] = acc[mi][j][half * 2 + 1] + b1;
                }
            }
        }
        __syncthreads();
        #pragma unroll 4
        for (int i = 0; i < 64; ++i) {
            int idx = i * 256 + tid;
            int cl = idx >> 7, rl = idx & 127;
            int row = m0 + rl;
            int b = row / Nspat, n = row - b * Nspat;
            Cf[((size_t)(b * Cc + n0 + cl)) * Nspat + n] = smf[rl * 129 + cl];
        }
        return;
    }

    #pragma unroll
    for (int mi = 0; mi < 2; ++mi) {
        int row0 = m0 + wm * 32 + mi * 16 + (lane >> 2);
        #pragma unroll
        for (int j = 0; j < 8; ++j) {
            int col0 = n0 + wn * 64 + j * 8 + (lane & 3) * 2;
            if (col0 >= Nc) continue;
            float b0 = bias[col0], b1 = bias[col0 + 1];
            #pragma unroll
            for (int half = 0; half < 2; ++half) {
                int row = row0 + half * 8;
                float v0 = acc[mi][j][half * 2 + 0] + b0;
                float v1 = acc[mi][j][half * 2 + 1] + b1;
                if (omode == 2) {
                    v0 = fmaxf(v0, 0.f); v1 = fmaxf(v1, 0.f);
                    *(__half2*)(CH + (size_t)row * Nc + col0) = __floats2half2_rn(v0, v1);
                } else {
                    if (act == 2) {
                        v0 = fminf(fmaxf(v0, -3.f), 3.f);
                        v1 = fminf(fmaxf(v1, -3.f), 3.f);
                    }
                    *(float2*)(Cf + (size_t)row * Nc + col0) = make_float2(v0, v1);
                }
            }
        }
    }
}

template<int ACT, int OMODE>
__global__ void __launch_bounds__(256, 2) k_sgemm(
    const __half* __restrict__ AH,
    const __half* __restrict__ Bs,
    const float* __restrict__ bias,
    float* __restrict__ Cf, __half* __restrict__ CH,
    int Nc)
{
    extern __shared__ __align__(1024) char sm_dyn[];
    sgemm_body(AH, Bs, bias, Cf, CH, Nc, ACT, OMODE,
               blockIdx.y * 128, blockIdx.x * 128, sm_dyn);
}

// dual: blocks [0,125) -> off = clip(hid@Wo2+bo2); [125,250) -> attn = q@W1[512:]+bc[512:]
__global__ void __launch_bounds__(256, 2) k_sgemm_dual(
    const __half* __restrict__ hid, const __half* __restrict__ wo2, const float* __restrict__ bo2,
    float* __restrict__ off,
    const __half* __restrict__ q, const __half* __restrict__ w1a, const float* __restrict__ bca,
    float* __restrict__ attn)
{
    extern __shared__ __align__(1024) char sm_dyn[];
    int by = blockIdx.y;
    if (by < 125)
        sgemm_body(hid, wo2, bo2, off, nullptr, NHc * NPc * 3, 2, 0, by * 128, 0, sm_dyn);
    else
        sgemm_body(q, w1a, bca, attn, nullptr, NHc * NPc, 0, 0, (by - 125) * 128, 0, sm_dyn);
}

// ---------------- merged prep: wprep(Wout), wprep(Wo2), wfold, bprep ----------------
// grid (16,16,23), block (32,8):
//   z==0 -> Wout transpose (bx,by full)
//   z==1 -> Wo2 transpose (guard n0<128)
//   z in [2,22) -> wfold row-group n0=(z-2)*32, j0=bx*32 (guard by==0)
//   z==22 -> bias prep (guard by==0, bx<3)
__global__ void k_prep(const float* __restrict__ Wout, const float* __restrict__ Wo2,
                       const float* __restrict__ Wo1,  const float* __restrict__ Wa,
                       const float* __restrict__ Wq,
                       const float* __restrict__ bq,   const float* __restrict__ bo1,
                       const float* __restrict__ ba) {
    __shared__ float T1[32][33];
    __shared__ float T2[32][33];
    int z = blockIdx.z;
    int tx = threadIdx.x, ty = threadIdx.y;
    if (z < 2) {
        const float* W = (z == 0) ? Wout : Wo2;
        __half* Hd = (z == 0) ? g_Wout : g_Wo2;
        int Ncols = (z == 0) ? 512 : NHc * NPc * 3;
        int Npad  = (z == 0) ? 512 : 128;
        int k0 = blockIdx.y * 32, n0 = blockIdx.x * 32;
        if (n0 >= Npad) return;
        #pragma unroll
        for (int i = 0; i < 32; i += 8) {
            int k = k0 + ty + i, n = n0 + tx;
            T1[ty + i][tx] = (n < Ncols) ? W[(size_t)k * Ncols + n] : 0.f;
        }
        __syncthreads();
        #pragma unroll
        for (int i = 0; i < 32; i += 8) {
            int n = n0 + ty + i, k = k0 + tx;
            Hd[(size_t)n * 512 + k] = __float2half_rn(T1[tx][ty + i]);
        }
        return;
    }
    if (z < 22) {
        if (blockIdx.y != 0) return;
        int n0 = (z - 2) * 32, j0 = blockIdx.x * 32;
        float acc[4] = {0.f, 0.f, 0.f, 0.f};
        for (int k0 = 0; k0 < 512; k0 += 32) {
            #pragma unroll
            for (int i = 0; i < 32; i += 8) {
                int k = k0 + ty + i, n = n0 + tx;
                float v = 0.f;
                if (n < 512)      v = Wo1[(size_t)k * 512 + n];
                else if (n < 544) v = Wa[(size_t)k * 32 + (n - 512)];
                T1[ty + i][tx] = v;
                T2[ty + i][tx] = Wq[(size_t)(j0 + ty + i) * 512 + k0 + tx];
            }
            __syncthreads();
            #pragma unroll 8
            for (int k = 0; k < 32; ++k) {
                float t1 = T1[k][tx];
                #pragma unroll
                for (int r = 0; r < 4; ++r) acc[r] += t1 * T2[ty + 8 * r][k];
            }
            __syncthreads();
        }
        #pragma unroll
        for (int r = 0; r < 4; ++r)
            g_W1[(size_t)(n0 + tx) * 512 + j0 + ty + 8 * r] = __float2half_rn(acc[r]);
        return;
    }
    // z == 22: bias
    if (blockIdx.y != 0 || blockIdx.x >= 3) return;
    int n = blockIdx.x * 256 + ty * 32 + tx;
    if (n >= 640) return;
    float s = 0.f;
    if (n < 512) {
        s = bo1[n];
        for (int j = 0; j < 512; ++j) s += bq[j] * Wo1[(size_t)j * 512 + n];
    } else if (n < 544) {
        int c = n - 512;
        s = ba[c];
        for (int j = 0; j < 512; ++j) s += bq[j] * Wa[(size_t)j * 32 + c];
    }
    g_bc[n] = s;
}

// ---------------- fused stats + transpose + LN -> fp16 q (fp16 tile, 6 CTA/SM) ----------------
// smem: half tile[32][514] + float sred[2][8][32] + float smean/srstd[32]
#define LN_SMEM (32*514*2 + 2*8*32*4 + 64*4)
__global__ void __launch_bounds__(256) k_lnfuse(const float* __restrict__ fq,
                                                const float* __restrict__ lng,
                                                const float* __restrict__ lnb) {
    extern __shared__ __align__(16) char sm_dyn[];
    __half* tile = (__half*)sm_dyn;                       // [32][514]
    float* sredS  = (float*)(sm_dyn + 32 * 514 * 2);      // [8][32]
    float* sredSS = sredS + 8 * 32;                       // [8][32]
    float* smean  = sredSS + 8 * 32;
    float* srstd  = smean + 32;
    int b  = blockIdx.y;
    int n0 = blockIdx.x * 32;
    int tid = threadIdx.x;
    int warp = tid >> 5, lane = tid & 31;
    // thread (warp,lane): token = lane, channels warp, warp+8, ...
    const float* src = fq + (size_t)b * Cc * Nspat + n0 + lane;
    float s = 0.f, ss = 0.f;
    #pragma unroll 8
    for (int it = 0; it < 64; ++it) {
        int c = it * 8 + warp;
        float v = src[(size_t)c * Nspat];
        s += v; ss += v * v;
        tile[lane * 514 + c] = __float2half_rn(v);
    }
    sredS[warp * 32 + lane] = s;
    sredSS[warp * 32 + lane] = ss;
    __syncthreads();
    if (warp == 0) {
        float st = 0.f, sst = 0.f;
        #pragma unroll
        for (int w = 0; w < 8; ++w) {
            st  += sredS[w * 32 + lane];
            sst += sredSS[w * 32 + lane];
        }
        float mu = st * (1.f / Cc);
        float var = sst * (1.f / Cc) - mu * mu;
        smean[lane] = mu;
        srstd[lane] = rsqrtf(var + LN_EPS);
    }
    __syncthreads();
    #pragma unroll
    for (int i = 0; i < 4; ++i) {
        int tok = warp * 4 + i;
        float mu = smean[tok], rs = srstd[tok];
        size_t obase = (size_t)(b * Nspat + n0 + tok) * Cc;
        const __half* row = tile + tok * 514;
        #pragma unroll
        for (int k = 0; k < 4; ++k) {
            int c = lane * 4 + k * 128;
            float2 va = __half22float2(*(const __half2*)(row + c));
            float2 vb = __half22float2(*(const __half2*)(row + c + 2));
            float v0 = (va.x - mu) * rs * lng[c + 0] + lnb[c + 0];
            float v1 = (va.y - mu) * rs * lng[c + 1] + lnb[c + 1];
            float v2 = (vb.x - mu) * rs * lng[c + 2] + lnb[c + 2];
            float v3 = (vb.y - mu) * rs * lng[c + 3] + lnb[c + 3];
            __half2 h01 = __floats2half2_rn(v0, v1);
            __half2 h23 = __floats2half2_rn(v2, v3);
            *(uint2*)(g_q + obase + c) = make_uint2(*(uint32_t*)&h01, *(uint32_t*)&h23);
        }
    }
}

// ---------------- permute f_kv -> (B,NH,D,H,W,HD) as fp16 ----------------
__global__ void k_perm(const float* __restrict__ fkv) {
    __shared__ float s[HDc * 21];
    int blk = blockIdx.x;
    int x = blk % Dim;
    int y = (blk / Dim) % Dim;
    int h = (blk / (Dim * Dim)) % NHc;
    int b = blk / (Dim * Dim * NHc);
    const float* src = fkv + ((size_t)(b * Cc + h * HDc)) * Nspat + (y * Dim + x) * Dim;
    for (int idx = threadIdx.x; idx < HDc * Dim; idx += blockDim.x) {
        int hd = idx / Dim, z = idx - hd * Dim;
        s[hd * 21 + z] = src[(size_t)hd * Nspat + z];
    }
    __syncthreads();
    __half* dst = g_feats + ((size_t)(b * NHc + h) * Nspat) * HDc;
    for (int idx = threadIdx.x; idx < HDc * Dim; idx += blockDim.x) {
        int z = idx / HDc, hd = idx - z * HDc;
        dst[(size_t)((z * Dim + y) * Dim + x) * HDc + hd] = __float2half_rn(s[hd * 21 + z]);
    }
}

// ---------------- trilinear gather + fused softmax + weighted sum ----------------
__global__ void k_sample() {
    int gw   = (blockIdx.x * blockDim.x + threadIdx.x) >> 5;
    int lane = threadIdx.x & 31;
    if (gw >= MTOT * NHc) return;
    int h = gw % NHc;
    int t = gw / NHc;
    int b = t / Nspat;
    int n = t - b * Nspat;
    int y = n / (Dim * Dim);
    int x = (n / Dim) % Dim;
    int z = n % Dim;

    const float* off = g_off + (size_t)gw * NPc * 3;
    float4 lg = ((const float4*)g_attn)[gw];
    float mx = fmaxf(fmaxf(lg.x, lg.y), fmaxf(lg.z, lg.w));
    float e0 = __expf(lg.x - mx), e1 = __expf(lg.y - mx);
    float e2 = __expf(lg.z - mx), e3 = __expf(lg.w - mx);
    float inv = 1.f / (e0 + e1 + e2 + e3);
    float aw[4] = {e0 * inv, e1 * inv, e2 * inv, e3 * inv};

    const __half* feats = g_feats + ((size_t)(b * NHc + h) * Nspat) * HDc;

    float acc0 = 0.f, acc1 = 0.f;
    #pragma unroll
    for (int p = 0; p < NPc; ++p) {
        float ap = aw[p];
        float ix = fminf(fmaxf((float)y + off[p * 3 + 0], 0.f), (float)(Dim - 1));
        float iy = fminf(fmaxf((float)x + off[p * 3 + 1], 0.f), (float)(Dim - 1));
        float iz = fminf(fmaxf((float)z + off[p * 3 + 2], 0.f), (float)(Dim - 1));
        float x0f = floorf(ix), y0f = floorf(iy), z0f = floorf(iz);
        float fx = ix - x0f, fy = iy - y0f, fz = iz - z0f;
        int x0 = (int)x0f, y0 = (int)y0f, z0 = (int)z0f;
        int x1 = min(x0 + 1, Dim - 1);
        int y1 = min(y0 + 1, Dim - 1);
        int z1 = min(z0 + 1, Dim - 1);
        float wx[2] = {1.f - fx, fx};
        float wy[2] = {1.f - fy, fy};
        float wz[2] = {1.f - fz, fz};
        int   xs[2] = {x0, x1}, ys[2] = {y0, y1}, zs[2] = {z0, z1};
        #pragma unroll
        for (int dz = 0; dz < 2; ++dz)
            #pragma unroll
            for (int dy = 0; dy < 2; ++dy)
                #pragma unroll
                for (int dx = 0; dx < 2; ++dx) {
                    float w = ap * wz[dz] * wy[dy] * wx[dx];
                    const __half2* f = (const __half2*)(feats + (size_t)((zs[dz] * Dim + ys[dy]) * Dim + xs[dx]) * HDc);
                    float2 v = __half22float2(f[lane]);
                    acc0 += w * v.x;
                    acc1 += w * v.y;
                }
    }
    *(__half2*)(g_s + (size_t)t * Cc + h * HDc + lane * 2) = __floats2half2_rn(acc0, acc1);
}

// ---------------- host ----------------
extern "C" void kernel_launch(void* const* d_in, const int* in_sizes, int n_in,
                              void* d_out, int out_size) {
    (void)in_sizes; (void)n_in; (void)out_size;
    const float* f_query = (const float*)d_in[0];
    const float* f_kv    = (const float*)d_in[1];
    const float* ln_g    = (const float*)d_in[2];
    const float* ln_b    = (const float*)d_in[3];
    const float* Wq   = (const float*)d_in[4];
    const float* bq   = (const float*)d_in[5];
    const float* Wo1  = (const float*)d_in[6];
    const float* bo1  = (const float*)d_in[7];
    const float* Wo2  = (const float*)d_in[8];
    const float* bo2  = (const float*)d_in[9];
    const float* Wa   = (const float*)d_in[10];
    const float* ba   = (const float*)d_in[11];
    const float* Wout = (const float*)d_in[12];
    const float* bout = (const float*)d_in[13];
    float* out = (float*)d_out;

    float *p_off, *p_attn, *p_bc;
    cudaGetSymbolAddress((void**)&p_off,  g_off);
    cudaGetSymbolAddress((void**)&p_attn, g_attn);
    cudaGetSymbolAddress((void**)&p_bc,   g_bc);
    __half *q, *hid, *sp, *w1, *wo2, *wo;
    cudaGetSymbolAddress((void**)&q, g_q);
    cudaGetSymbolAddress((void**)&hid, g_hid);
    cudaGetSymbolAddress((void**)&sp, g_s);
    cudaGetSymbolAddress((void**)&w1, g_W1);
    cudaGetSymbolAddress((void**)&wo2, g_Wo2);
    cudaGetSymbolAddress((void**)&wo, g_Wout);

    cudaFuncSetAttribute((const void*)k_sgemm<0,2>, cudaFuncAttributeMaxDynamicSharedMemorySize, NS_SMEM);
    cudaFuncSetAttribute((const void*)k_sgemm_dual, cudaFuncAttributeMaxDynamicSharedMemorySize, NS_SMEM);
    cudaFuncSetAttribute((const void*)k_sgemm<0,1>, cudaFuncAttributeMaxDynamicSharedMemorySize, TR_SMEM);
    cudaFuncSetAttribute(k_lnfuse, cudaFuncAttributeMaxDynamicSharedMemorySize, LN_SMEM);

    // one merged prep launch
    k_prep<<<dim3(16, 16, 23), dim3(32, 8)>>>(Wout, Wo2, Wo1, Wa, Wq, bq, bo1, ba);

    // fused stats + transpose + LN -> fp16 q
    k_lnfuse<<<dim3(250, Bc), 256, LN_SMEM>>>(f_query, ln_g, ln_b);
    // permute KV to fp16 channels-last
    k_perm<<<Bc * NHc * Dim * Dim, 256>>>(f_kv);

    // hid = relu(q @ W1[0:512] + bc) -> fp16   (500 blocks)
    k_sgemm<0,2><<<dim3(4, 125), 256, NS_SMEM>>>(q, w1, p_bc, nullptr, hid, Cc);
    // off = clip(hid@Wo2+bo2)  AND  attn = q@W1[512:544]+bc[512:]   (250 blocks, one wave)
    k_sgemm_dual<<<dim3(1, 250), 256, NS_SMEM>>>(hid, wo2, bo2, p_off,
                                                 q, w1 + (size_t)512 * 512, p_bc + 512, p_attn);
    // sampling (softmax fused) -> fp16 samp
    k_sample<<<(MTOT * NHc) * 32 / 256, 256>>>();
    // out = samp @ Wout + bout, staged coalesced transposed store
    k_sgemm<0,1><<<dim3(4, 125), 256, TR_SMEM>>>(sp, wo, bout, out, nullptr, Cc);
}

// round 13
// speedup vs baseline: 1.5900x; 1.0090x over previous
#include <cuda_runtime.h>
#include <cuda_bf16.h>
#include <cuda_fp16.h>
#include <cstdint>

#define Bc 2
#define Cc 512
#define NHc 8
#define NPc 4
#define HDc 64
#define Dim 20
#define Nspat 8000          // 20*20*20
#define MTOT (Bc*Nspat)     // 16000
#define LN_EPS 1e-5f

// ---------------- scratch ----------------
__device__ __align__(16) __half g_q   [(size_t)MTOT*Cc];
__device__ __align__(16) __half g_hid [(size_t)MTOT*Cc];
__device__ __align__(16) __half g_s   [(size_t)MTOT*Cc];
__device__ __align__(16) float g_off [(size_t)MTOT*NHc*NPc*3];
__device__ __align__(16) float g_attn[(size_t)MTOT*NHc*NPc];
__device__ __align__(16) __half g_feats[(size_t)Bc*NHc*Nspat*HDc];
__device__ __align__(256) __half g_W1  [640*512];   // folded [Wo1T;WaT]@Wq
__device__ __align__(256) __half g_Wo2 [128*512];
__device__ __align__(256) __half g_Wout[512*512];
__device__ float g_bc[640];

// ================= helpers =================
__device__ __forceinline__ uint32_t smem_u32(const void* p) {
    uint32_t a;
    asm("{ .reg .u64 t; cvta.to.shared.u64 t, %1; cvt.u32.u64 %0, t; }" : "=r"(a) : "l"(p));
    return a;
}
__device__ __forceinline__ void ldsm4(uint32_t* r, uint32_t addr) {
    asm volatile("ldmatrix.sync.aligned.m8n8.x4.shared.b16 {%0,%1,%2,%3}, [%4];"
        : "=r"(r[0]), "=r"(r[1]), "=r"(r[2]), "=r"(r[3]) : "r"(addr));
}
__device__ __forceinline__ void mma_f16(float* c, const uint32_t* a, const uint32_t* b) {
    asm volatile(
        "mma.sync.aligned.m16n8k16.row.col.f32.f16.f16.f32 "
        "{%0,%1,%2,%3}, {%4,%5,%6,%7}, {%8,%9}, {%0,%1,%2,%3};"
        : "+f"(c[0]), "+f"(c[1]), "+f"(c[2]), "+f"(c[3])
        : "r"(a[0]), "r"(a[1]), "r"(a[2]), "r"(a[3]), "r"(b[0]), "r"(b[1]));
}
#define CPA16(dst, src) \
    asm volatile("cp.async.cg.shared.global [%0], [%1], 16;" :: "r"(dst), "l"(src) : "memory")

// ================= fp16 HMMA GEMM (single-A, 3-stage cp.async) =================
// Tile 128x128, BK=32. stage: A@0 B@10240 (20480B). 3 stages = 61440B.
#define GM_STAGE 20480
#define NS_SMEM (3*GM_STAGE)   // 61440
#define TR_SMEM (128*129*4)    // 66048 for staged transposed epilogue (>= NS_SMEM)

// omode: 0 = fp32 row-major (+act: 0 none, 2 clip), 1 = fp32 transposed staged,
//        2 = relu -> fp16
__device__ __forceinline__ void sgemm_body(
    const __half* __restrict__ AH,
    const __half* __restrict__ Bs,
    const float* __restrict__ bias,
    float* __restrict__ Cf, __half* __restrict__ CH,
    int Nc, int act, int omode, int m0, int n0, char* sm)
{
    constexpr int BOFF = 10240;
    const uint32_t smb = smem_u32(sm);
    const int tid = threadIdx.x;
    const int wid = tid >> 5, lane = tid & 31;
    const int wm = wid >> 1;
    const int wn = wid & 1;

    const int tq = lane >> 3, rr = lane & 7;
    const int a_row = rr + (tq & 1) * 8;
    const int a_col = (tq >> 1) * 8;
    const int b_row = rr + (tq >> 1) * 8;
    const int b_col = (tq & 1) * 8;

    const int r2  = tid >> 1;
    const int kc2 = (tid & 1) * 32;

    const __half* AHp = AH + (size_t)(m0 + r2) * 512 + (tid & 1) * 16;
    const __half* Bp  = Bs + (size_t)(n0 + r2) * 512 + (tid & 1) * 16;

    auto ldAB = [&](int buf, int kt) {
        uint32_t ro = smb + buf * GM_STAGE + r2 * 80 + kc2;
        const int go = kt * 32;
        CPA16(ro,             AHp + go);
        CPA16(ro + 16,        AHp + go + 8);
        CPA16(ro + BOFF,      Bp + go);
        CPA16(ro + BOFF + 16, Bp + go + 8);
        asm volatile("cp.async.commit_group;" ::: "memory");
    };

    float acc[2][8][4];
    #pragma unroll
    for (int mi = 0; mi < 2; ++mi)
        #pragma unroll
        for (int j = 0; j < 8; ++j)
            #pragma unroll
            for (int q = 0; q < 4; ++q) acc[mi][j][q] = 0.f;

    ldAB(0, 0);
    ldAB(1, 1);

    int buf = 0;
    for (int kt = 0; kt < 16; ++kt) {
        if (kt + 2 < 16) {
            // buf (kt+2)%3 was consumed at iteration kt-1 and synced after
            ldAB((buf + 2) % 3, kt + 2);
            asm volatile("cp.async.wait_group 2;" ::: "memory");
        } else if (kt + 1 < 16) {
            asm volatile("cp.async.wait_group 1;" ::: "memory");
        } else {
            asm volatile("cp.async.wait_group 0;" ::: "memory");
        }
        __syncthreads();
        uint32_t abase = smb + buf * GM_STAGE;
        uint32_t bbase = abase + BOFF;
        #pragma unroll
        for (int ks = 0; ks < 2; ++ks) {
            int kc = ks * 16;
            uint32_t ah[2][4], bf[4][4];
            #pragma unroll
            for (int mi = 0; mi < 2; ++mi) {
                uint32_t ad = abase + (uint32_t)(wm * 32 + mi * 16 + a_row) * 80 + (kc + a_col) * 2;
                ldsm4(ah[mi], ad);
            }
            #pragma unroll
            for (int p = 0; p < 4; ++p) {
                uint32_t bd = bbase + (uint32_t)(wn * 64 + p * 16 + b_row) * 80 + (kc + b_col) * 2;
                ldsm4(bf[p], bd);
            }
            #pragma unroll
            for (int mi = 0; mi < 2; ++mi)
                #pragma unroll
                for (int j = 0; j < 8; ++j)
                    mma_f16(acc[mi][j], ah[mi], &bf[j >> 1][(j & 1) * 2]);
        }
        __syncthreads();
        buf = (buf + 1) % 3;
    }

    if (omode == 1) {
        float* smf = (float*)sm;   // [128][129]
        #pragma unroll
        for (int mi = 0; mi < 2; ++mi) {
            #pragma unroll
            for (int j = 0; j < 8; ++j) {
                int c0 = wn * 64 + j * 8 + (lane & 3) * 2;
                float b0 = bias[n0 + c0], b1 = bias[n0 + c0 + 1];
                #pragma unroll
                for (int half = 0; half < 2; ++half) {
                    int r = wm * 32 + mi * 16 + (lane >> 2) + half * 8;
                    smf[r * 129 + c0]     = acc[mi][j][half * 2 + 0] + b0;
                    smf[r * 129 + c0 + 1] = acc[mi][j][half * 2 + 1] + b1;
                }
            }
        }
        __syncthreads();
        #pragma unroll 4
        for (int i = 0; i < 64; ++i) {
            int idx = i * 256 + tid;
            int cl = idx >> 7, rl = idx & 127;
            int row = m0 + rl;
            int b = row / Nspat, n = row - b * Nspat;
            Cf[((size_t)(b * Cc + n0 + cl)) * Nspat + n] = smf[rl * 129 + cl];
        }
        return;
    }

    #pragma unroll
    for (int mi = 0; mi < 2; ++mi) {
        int row0 = m0 + wm * 32 + mi * 16 + (lane >> 2);
        #pragma unroll
        for (int j = 0; j < 8; ++j) {
            int col0 = n0 + wn * 64 + j * 8 + (lane & 3) * 2;
            if (col0 >= Nc) continue;
            float b0 = bias[col0], b1 = bias[col0 + 1];
            #pragma unroll
            for (int half = 0; half < 2; ++half) {
                int row = row0 + half * 8;
                float v0 = acc[mi][j][half * 2 + 0] + b0;
                float v1 = acc[mi][j][half * 2 + 1] + b1;
                if (omode == 2) {
                    v0 = fmaxf(v0, 0.f); v1 = fmaxf(v1, 0.f);
                    *(__half2*)(CH + (size_t)row * Nc + col0) = __floats2half2_rn(v0, v1);
                } else {
                    if (act == 2) {
                        v0 = fminf(fmaxf(v0, -3.f), 3.f);
                        v1 = fminf(fmaxf(v1, -3.f), 3.f);
                    }
                    *(float2*)(Cf + (size_t)row * Nc + col0) = make_float2(v0, v1);
                }
            }
        }
    }
}

template<int ACT, int OMODE>
__global__ void __launch_bounds__(256, 2) k_sgemm(
    const __half* __restrict__ AH,
    const __half* __restrict__ Bs,
    const float* __restrict__ bias,
    float* __restrict__ Cf, __half* __restrict__ CH,
    int Nc)
{
    extern __shared__ __align__(1024) char sm_dyn[];
    sgemm_body(AH, Bs, bias, Cf, CH, Nc, ACT, OMODE,
               blockIdx.y * 128, blockIdx.x * 128, sm_dyn);
}

// dual: blocks [0,125) -> off = clip(hid@Wo2+bo2); [125,250) -> attn = q@W1[512:]+bc[512:]
__global__ void __launch_bounds__(256, 2) k_sgemm_dual(
    const __half* __restrict__ hid, const __half* __restrict__ wo2, const float* __restrict__ bo2,
    float* __restrict__ off,
    const __half* __restrict__ q, const __half* __restrict__ w1a, const float* __restrict__ bca,
    float* __restrict__ attn)
{
    extern __shared__ __align__(1024) char sm_dyn[];
    int by = blockIdx.y;
    if (by < 125)
        sgemm_body(hid, wo2, bo2, off, nullptr, NHc * NPc * 3, 2, 0, by * 128, 0, sm_dyn);
    else
        sgemm_body(q, w1a, bca, attn, nullptr, NHc * NPc, 0, 0, (by - 125) * 128, 0, sm_dyn);
}

// ---------------- merged prep ----------------
__global__ void k_prep(const float* __restrict__ Wout, const float* __restrict__ Wo2,
                       const float* __restrict__ Wo1,  const float* __restrict__ Wa,
                       const float* __restrict__ Wq,
                       const float* __restrict__ bq,   const float* __restrict__ bo1,
                       const float* __restrict__ ba) {
    __shared__ float T1[32][33];
    __shared__ float T2[32][33];
    int z = blockIdx.z;
    int tx = threadIdx.x, ty = threadIdx.y;
    if (z < 2) {
        const float* W = (z == 0) ? Wout : Wo2;
        __half* Hd = (z == 0) ? g_Wout : g_Wo2;
        int Ncols = (z == 0) ? 512 : NHc * NPc * 3;
        int Npad  = (z == 0) ? 512 : 128;
        int k0 = blockIdx.y * 32, n0 = blockIdx.x * 32;
        if (n0 >= Npad) return;
        #pragma unroll
        for (int i = 0; i < 32; i += 8) {
            int k = k0 + ty + i, n = n0 + tx;
            T1[ty + i][tx] = (n < Ncols) ? W[(size_t)k * Ncols + n] : 0.f;
        }
        __syncthreads();
        #pragma unroll
        for (int i = 0; i < 32; i += 8) {
            int n = n0 + ty + i, k = k0 + tx;
            Hd[(size_t)n * 512 + k] = __float2half_rn(T1[tx][ty + i]);
        }
        return;
    }
    if (z < 22) {
        if (blockIdx.y != 0) return;
        int n0 = (z - 2) * 32, j0 = blockIdx.x * 32;
        float acc[4] = {0.f, 0.f, 0.f, 0.f};
        for (int k0 = 0; k0 < 512; k0 += 32) {
            #pragma unroll
            for (int i = 0; i < 32; i += 8) {
                int k = k0 + ty + i, n = n0 + tx;
                float v = 0.f;
                if (n < 512)      v = Wo1[(size_t)k * 512 + n];
                else if (n < 544) v = Wa[(size_t)k * 32 + (n - 512)];
                T1[ty + i][tx] = v;
                T2[ty + i][tx] = Wq[(size_t)(j0 + ty + i) * 512 + k0 + tx];
            }
            __syncthreads();
            #pragma unroll 8
            for (int k = 0; k < 32; ++k) {
                float t1 = T1[k][tx];
                #pragma unroll
                for (int r = 0; r < 4; ++r) acc[r] += t1 * T2[ty + 8 * r][k];
            }
            __syncthreads();
        }
        #pragma unroll
        for (int r = 0; r < 4; ++r)
            g_W1[(size_t)(n0 + tx) * 512 + j0 + ty + 8 * r] = __float2half_rn(acc[r]);
        return;
    }
    if (blockIdx.y != 0 || blockIdx.x >= 3) return;
    int n = blockIdx.x * 256 + ty * 32 + tx;
    if (n >= 640) return;
    float s = 0.f;
    if (n < 512) {
        s = bo1[n];
        for (int j = 0; j < 512; ++j) s += bq[j] * Wo1[(size_t)j * 512 + n];
    } else if (n < 544) {
        int c = n - 512;
        s = ba[c];
        for (int j = 0; j < 512; ++j) s += bq[j] * Wa[(size_t)j * 32 + c];
    }
    g_bc[n] = s;
}

// ---------------- fused stats + transpose + LN -> fp16 q (fp16 tile) ----------------
#define LN_SMEM (32*514*2 + 2*8*32*4 + 64*4)
__global__ void __launch_bounds__(256) k_lnfuse(const float* __restrict__ fq,
                                                const float* __restrict__ lng,
                                                const float* __restrict__ lnb) {
    extern __shared__ __align__(16) char sm_dyn[];
    __half* tile = (__half*)sm_dyn;
    float* sredS  = (float*)(sm_dyn + 32 * 514 * 2);
    float* sredSS = sredS + 8 * 32;
    float* smean  = sredSS + 8 * 32;
    float* srstd  = smean + 32;
    int b  = blockIdx.y;
    int n0 = blockIdx.x * 32;
    int tid = threadIdx.x;
    int warp = tid >> 5, lane = tid & 31;
    const float* src = fq + (size_t)b * Cc * Nspat + n0 + lane;
    float s = 0.f, ss = 0.f;
    #pragma unroll 8
    for (int it = 0; it < 64; ++it) {
        int c = it * 8 + warp;
        float v = src[(size_t)c * Nspat];
        s += v; ss += v * v;
        tile[lane * 514 + c] = __float2half_rn(v);
    }
    sredS[warp * 32 + lane] = s;
    sredSS[warp * 32 + lane] = ss;
    __syncthreads();
    if (warp == 0) {
        float st = 0.f, sst = 0.f;
        #pragma unroll
        for (int w = 0; w < 8; ++w) {
            st  += sredS[w * 32 + lane];
            sst += sredSS[w * 32 + lane];
        }
        float mu = st * (1.f / Cc);
        float var = sst * (1.f / Cc) - mu * mu;
        smean[lane] = mu;
        srstd[lane] = rsqrtf(var + LN_EPS);
    }
    __syncthreads();
    #pragma unroll
    for (int i = 0; i < 4; ++i) {
        int tok = warp * 4 + i;
        float mu = smean[tok], rs = srstd[tok];
        size_t obase = (size_t)(b * Nspat + n0 + tok) * Cc;
        const __half* row = tile + tok * 514;
        #pragma unroll
        for (int k = 0; k < 4; ++k) {
            int c = lane * 4 + k * 128;
            float2 va = __half22float2(*(const __half2*)(row + c));
            float2 vb = __half22float2(*(const __half2*)(row + c + 2));
            float v0 = (va.x - mu) * rs * lng[c + 0] + lnb[c + 0];
            float v1 = (va.y - mu) * rs * lng[c + 1] + lnb[c + 1];
            float v2 = (vb.x - mu) * rs * lng[c + 2] + lnb[c + 2];
            float v3 = (vb.y - mu) * rs * lng[c + 3] + lnb[c + 3];
            __half2 h01 = __floats2half2_rn(v0, v1);
            __half2 h23 = __floats2half2_rn(v2, v3);
            *(uint2*)(g_q + obase + c) = make_uint2(*(uint32_t*)&h01, *(uint32_t*)&h23);
        }
    }
}

// ---------------- permute f_kv -> (B,NH,D,H,W,HD) as fp16 ----------------
__global__ void k_perm(const float* __restrict__ fkv) {
    __shared__ float s[HDc * 21];
    int blk = blockIdx.x;
    int x = blk % Dim;
    int y = (blk / Dim) % Dim;
    int h = (blk / (Dim * Dim)) % NHc;
    int b = blk / (Dim * Dim * NHc);
    const float* src = fkv + ((size_t)(b * Cc + h * HDc)) * Nspat + (y * Dim + x) * Dim;
    for (int idx = threadIdx.x; idx < HDc * Dim; idx += blockDim.x) {
        int hd = idx / Dim, z = idx - hd * Dim;
        s[hd * 21 + z] = src[(size_t)hd * Nspat + z];
    }
    __syncthreads();
    __half* dst = g_feats + ((size_t)(b * NHc + h) * Nspat) * HDc;
    for (int idx = threadIdx.x; idx < HDc * Dim; idx += blockDim.x) {
        int z = idx / HDc, hd = idx - z * HDc;
        dst[(size_t)((z * Dim + y) * Dim + x) * HDc + hd] = __float2half_rn(s[hd * 21 + z]);
    }
}

// ---------------- trilinear gather + fused softmax + weighted sum ----------------
__global__ void k_sample() {
    int gw   = (blockIdx.x * blockDim.x + threadIdx.x) >> 5;
    int lane = threadIdx.x & 31;
    if (gw >= MTOT * NHc) return;
    int h = gw % NHc;
    int t = gw / NHc;
    int b = t / Nspat;
    int n = t - b * Nspat;
    int y = n / (Dim * Dim);
    int x = (n / Dim) % Dim;
    int z = n % Dim;

    const float* off = g_off + (size_t)gw * NPc * 3;
    float4 lg = ((const float4*)g_attn)[gw];
    float mx = fmaxf(fmaxf(lg.x, lg.y), fmaxf(lg.z, lg.w));
    float e0 = __expf(lg.x - mx), e1 = __expf(lg.y - mx);
    float e2 = __expf(lg.z - mx), e3 = __expf(lg.w - mx);
    float inv = 1.f / (e0 + e1 + e2 + e3);
    float aw[4] = {e0 * inv, e1 * inv, e2 * inv, e3 * inv};

    const __half* feats = g_feats + ((size_t)(b * NHc + h) * Nspat) * HDc;

    float acc0 = 0.f, acc1 = 0.f;
    #pragma unroll
    for (int p = 0; p < NPc; ++p) {
        float ap = aw[p];
        float ix = fminf(fmaxf((float)y + off[p * 3 + 0], 0.f), (float)(Dim - 1));
        float iy = fminf(fmaxf((float)x + off[p * 3 + 1], 0.f), (float)(Dim - 1));
        float iz = fminf(fmaxf((float)z + off[p * 3 + 2], 0.f), (float)(Dim - 1));
        float x0f = floorf(ix), y0f = floorf(iy), z0f = floorf(iz);
        float fx = ix - x0f, fy = iy - y0f, fz = iz - z0f;
        int x0 = (int)x0f, y0 = (int)y0f, z0 = (int)z0f;
        int x1 = min(x0 + 1, Dim - 1);
        int y1 = min(y0 + 1, Dim - 1);
        int z1 = min(z0 + 1, Dim - 1);
        float wx[2] = {1.f - fx, fx};
        float wy[2] = {1.f - fy, fy};
        float wz[2] = {1.f - fz, fz};
        int   xs[2] = {x0, x1}, ys[2] = {y0, y1}, zs[2] = {z0, z1};
        #pragma unroll
        for (int dz = 0; dz < 2; ++dz)
            #pragma unroll
            for (int dy = 0; dy < 2; ++dy)
                #pragma unroll
                for (int dx = 0; dx < 2; ++dx) {
                    float w = ap * wz[dz] * wy[dy] * wx[dx];
                    const __half2* f = (const __half2*)(feats + (size_t)((zs[dz] * Dim + ys[dy]) * Dim + xs[dx]) * HDc);
                    float2 v = __half22float2(f[lane]);
                    acc0 += w * v.x;
                    acc1 += w * v.y;
                }
    }
    *(__half2*)(g_s + (size_t)t * Cc + h * HDc + lane * 2) = __floats2half2_rn(acc0, acc1);
}

// ---------------- host ----------------
extern "C" void kernel_launch(void* const* d_in, const int* in_sizes, int n_in,
                              void* d_out, int out_size) {
    (void)in_sizes; (void)n_in; (void)out_size;
    const float* f_query = (const float*)d_in[0];
    const float* f_kv    = (const float*)d_in[1];
    const float* ln_g    = (const float*)d_in[2];
    const float* ln_b    = (const float*)d_in[3];
    const float* Wq   = (const float*)d_in[4];
    const float* bq   = (const float*)d_in[5];
    const float* Wo1  = (const float*)d_in[6];
    const float* bo1  = (const float*)d_in[7];
    const float* Wo2  = (const float*)d_in[8];
    const float* bo2  = (const float*)d_in[9];
    const float* Wa   = (const float*)d_in[10];
    const float* ba   = (const float*)d_in[11];
    const float* Wout = (const float*)d_in[12];
    const float* bout = (const float*)d_in[13];
    float* out = (float*)d_out;

    float *p_off, *p_attn, *p_bc;
    cudaGetSymbolAddress((void**)&p_off,  g_off);
    cudaGetSymbolAddress((void**)&p_attn, g_attn);
    cudaGetSymbolAddress((void**)&p_bc,   g_bc);
    __half *q, *hid, *sp, *w1, *wo2, *wo;
    cudaGetSymbolAddress((void**)&q, g_q);
    cudaGetSymbolAddress((void**)&hid, g_hid);
    cudaGetSymbolAddress((void**)&sp, g_s);
    cudaGetSymbolAddress((void**)&w1, g_W1);
    cudaGetSymbolAddress((void**)&wo2, g_Wo2);
    cudaGetSymbolAddress((void**)&wo, g_Wout);

    cudaFuncSetAttribute((const void*)k_sgemm<0,2>, cudaFuncAttributeMaxDynamicSharedMemorySize, NS_SMEM);
    cudaFuncSetAttribute((const void*)k_sgemm_dual, cudaFuncAttributeMaxDynamicSharedMemorySize, NS_SMEM);
    cudaFuncSetAttribute((const void*)k_sgemm<0,1>, cudaFuncAttributeMaxDynamicSharedMemorySize, TR_SMEM);
    cudaFuncSetAttribute(k_lnfuse, cudaFuncAttributeMaxDynamicSharedMemorySize, LN_SMEM);

    // one merged prep launch
    k_prep<<<dim3(16, 16, 23), dim3(32, 8)>>>(Wout, Wo2, Wo1, Wa, Wq, bq, bo1, ba);

    // fused stats + transpose + LN -> fp16 q
    k_lnfuse<<<dim3(250, Bc), 256, LN_SMEM>>>(f_query, ln_g, ln_b);
    // permute KV to fp16 channels-last
    k_perm<<<Bc * NHc * Dim * Dim, 256>>>(f_kv);

    // hid = relu(q @ W1[0:512] + bc) -> fp16   (500 blocks)
    k_sgemm<0,2><<<dim3(4, 125), 256, NS_SMEM>>>(q, w1, p_bc, nullptr, hid, Cc);
    // off = clip(hid@Wo2+bo2)  AND  attn = q@W1[512:544]+bc[512:]   (250 blocks, one wave)
    k_sgemm_dual<<<dim3(1, 250), 256, NS_SMEM>>>(hid, wo2, bo2, p_off,
                                                 q, w1 + (size_t)512 * 512, p_bc + 512, p_attn);
    // sampling (softmax fused) -> fp16 samp
    k_sample<<<(MTOT * NHc) * 32 / 256, 256>>>();
    // out = samp @ Wout + bout, staged coalesced transposed store
    k_sgemm<0,1><<<dim3(4, 125), 256, TR_SMEM>>>(sp, wo, bout, out, nullptr, Cc);
}